// round 3
// baseline (speedup 1.0000x reference)
#include <cuda_runtime.h>
#include <cuda_bf16.h>
#include <mma.h>
using namespace nvcuda;

#define Bsz 16
#define Tsz 256
#define Esz 200
#define Hsz 256
#define Vsz 32000
#define G4  1024
#define Msz 4096   // B*T rows, time-major: r = t*16 + b

__device__ float g_x[Msz*Hsz];
__device__ float g_xg[Msz*G4];
__device__ float g_hall[Msz*Hsz];
__device__ float g_wi0p[G4*Hsz];
__device__ float g_hping[2*Bsz*Hsz];
__device__ __nv_bfloat16 g_hb[Msz*Hsz];
__device__ __nv_bfloat16 g_wb[(size_t)Vsz*Hsz];
__device__ unsigned g_barcnt = 0;
__device__ unsigned g_bargen = 0;

__device__ __forceinline__ float sigmoidf_(float x){ return 1.f/(1.f+__expf(-x)); }
__device__ __forceinline__ float tanhf_(float x){ return 1.f - 2.f/(__expf(2.f*x)+1.f); }

__global__ void embed_kernel(const int* __restrict__ x, const float* __restrict__ emb){
  int idx = blockIdx.x*256 + threadIdx.x;
  int r = idx >> 8, k = idx & 255;
  int t = r >> 4, b = r & 15;
  float v = 0.f;
  if (k < Esz) v = emb[(size_t)x[b*Tsz + t]*Esz + k];
  g_x[idx] = v;
}

__global__ void padwi0_kernel(const float* __restrict__ Wi0){
  int idx = blockIdx.x*256 + threadIdx.x;
  int j = idx >> 8, k = idx & 255;
  g_wi0p[idx] = (k < Esz) ? Wi0[j*Esz + k] : 0.f;
}

__global__ void convwb_kernel(const float* __restrict__ fcW){
  size_t idx = (size_t)blockIdx.x*256 + threadIdx.x;
  g_wb[idx] = __float2bfloat16(fcW[idx]);
}

__global__ void convhb_kernel(){
  int idx = blockIdx.x*256 + threadIdx.x;
  g_hb[idx] = __float2bfloat16(g_hall[idx]);
}

// input-proj GEMM: g_xg[r][n] = sum_k X[r][k]*W[n][k] + bias[n]
__global__ __launch_bounds__(256) void xproj_kernel(int sel,
                                                    const float* __restrict__ Wext,
                                                    const float* __restrict__ bias){
  const float* __restrict__ X = sel ? g_hall : g_x;
  const float* __restrict__ W = sel ? Wext  : g_wi0p;
  __shared__ float As[16][64];
  __shared__ float Bs[16][64];
  int tid = threadIdx.x;
  int tx = tid & 15, ty = tid >> 4;
  int m0 = blockIdx.y*64, n0 = blockIdx.x*64;
  int lr = tid >> 2, lc = (tid & 3)*4;
  float acc[4][4] = {};
  for (int k0 = 0; k0 < 256; k0 += 16){
    float4 xv = *(const float4*)&X[(m0+lr)*256 + k0 + lc];
    float4 wv = *(const float4*)&W[(n0+lr)*256 + k0 + lc];
    __syncthreads();
    As[lc][lr]=xv.x; As[lc+1][lr]=xv.y; As[lc+2][lr]=xv.z; As[lc+3][lr]=xv.w;
    Bs[lc][lr]=wv.x; Bs[lc+1][lr]=wv.y; Bs[lc+2][lr]=wv.z; Bs[lc+3][lr]=wv.w;
    __syncthreads();
    #pragma unroll
    for (int k = 0; k < 16; k++){
      float4 a = *(float4*)&As[k][ty*4];
      float4 b = *(float4*)&Bs[k][tx*4];
      acc[0][0]+=a.x*b.x; acc[0][1]+=a.x*b.y; acc[0][2]+=a.x*b.z; acc[0][3]+=a.x*b.w;
      acc[1][0]+=a.y*b.x; acc[1][1]+=a.y*b.y; acc[1][2]+=a.y*b.z; acc[1][3]+=a.y*b.w;
      acc[2][0]+=a.z*b.x; acc[2][1]+=a.z*b.y; acc[2][2]+=a.z*b.z; acc[2][3]+=a.z*b.w;
      acc[3][0]+=a.w*b.x; acc[3][1]+=a.w*b.y; acc[3][2]+=a.w*b.z; acc[3][3]+=a.w*b.w;
    }
  }
  #pragma unroll
  for (int i = 0; i < 4; i++){
    int mrow = m0 + ty*4 + i;
    #pragma unroll
    for (int j = 0; j < 4; j++){
      int n = n0 + tx*4 + j;
      g_xg[mrow*G4 + n] = acc[i][j] + bias[n];
    }
  }
}

__device__ __forceinline__ void gridbar(unsigned &gen){
  __threadfence();
  __syncthreads();
  if (threadIdx.x == 0){
    unsigned ticket = atomicAdd(&g_barcnt, 1u);
    if (ticket == gridDim.x - 1){
      g_barcnt = 0u;
      __threadfence();
      atomicAdd(&g_bargen, 1u);
    } else {
      while (*(volatile unsigned*)&g_bargen == gen) { }
    }
  }
  __syncthreads();
  __threadfence();
  gen++;
}

// persistent LSTM scan: 64 blocks x 128 threads, one layer, 256 steps
__global__ __launch_bounds__(128) void scan_kernel(const float* __restrict__ Wh){
  __shared__ float4 Whs[16][64];
  __shared__ float4 hsA[16][64];
  int tid = threadIdx.x;
  int ks  = tid & 7;
  int col = tid >> 3;
  int lj  = col >> 2;
  int bg  = col & 3;
  int jj  = blockIdx.x*4 + lj;

  const float4* Wh4 = (const float4*)Wh;
  for (int L = tid; L < 1024; L += 128){
    int row = L >> 6, k4 = L & 63;
    int l = row >> 2, g = row & 3;
    Whs[row][k4 ^ ((k4>>3)&7)] = Wh4[(g*256 + blockIdx.x*4 + l)*64 + k4];
  }

  float c[4] = {0.f,0.f,0.f,0.f};
  unsigned gen = *(volatile unsigned*)&g_bargen;

  if (ks == 0){
    #pragma unroll
    for (int j = 0; j < 4; j++) g_hping[(bg + 4*j)*256 + jj] = 0.f;
  }
  gridbar(gen);

  for (int t = 0; t < 256; t++){
    const float4* hcur = (const float4*)(g_hping + (t & 1)*4096);
    for (int i = tid; i < 1024; i += 128){
      int b = i >> 6, k4 = i & 63;
      hsA[b][k4 ^ ((k4>>3)&7)] = __ldcg(hcur + i);
    }
    __syncthreads();

    float acc[4][4];
    #pragma unroll
    for (int j = 0; j < 4; j++)
      #pragma unroll
      for (int g = 0; g < 4; g++) acc[j][g] = 0.f;

    #pragma unroll
    for (int u = 0; u < 8; u++){
      int phys = (ks*8 + u) ^ ks;
      float4 w0 = Whs[lj*4+0][phys];
      float4 w1 = Whs[lj*4+1][phys];
      float4 w2 = Whs[lj*4+2][phys];
      float4 w3 = Whs[lj*4+3][phys];
      #pragma unroll
      for (int j = 0; j < 4; j++){
        float4 hv = hsA[bg + 4*j][phys];
        acc[j][0] += hv.x*w0.x + hv.y*w0.y + hv.z*w0.z + hv.w*w0.w;
        acc[j][1] += hv.x*w1.x + hv.y*w1.y + hv.z*w1.z + hv.w*w1.w;
        acc[j][2] += hv.x*w2.x + hv.y*w2.y + hv.z*w2.z + hv.w*w2.w;
        acc[j][3] += hv.x*w3.x + hv.y*w3.y + hv.z*w3.z + hv.w*w3.w;
      }
    }
    #pragma unroll
    for (int off = 1; off < 8; off <<= 1)
      #pragma unroll
      for (int j = 0; j < 4; j++)
        #pragma unroll
        for (int g = 0; g < 4; g++)
          acc[j][g] += __shfl_xor_sync(0xffffffffu, acc[j][g], off);

    if (ks == 0){
      float* hnxt = g_hping + ((t+1) & 1)*4096;
      #pragma unroll
      for (int j = 0; j < 4; j++){
        int b = bg + 4*j;
        int base = (t*16 + b)*G4 + jj;
        float gi = acc[j][0] + g_xg[base];
        float gf = acc[j][1] + g_xg[base+256];
        float gc = acc[j][2] + g_xg[base+512];
        float go = acc[j][3] + g_xg[base+768];
        float iv = sigmoidf_(gi);
        float fv = sigmoidf_(gf);
        float cv = tanhf_(gc);
        float ov = sigmoidf_(go);
        c[j] = fv*c[j] + iv*cv;
        float hv = ov*tanhf_(c[j]);
        hnxt[b*256 + jj] = hv;
        g_hall[(t*16 + b)*256 + jj] = hv;
      }
    }
    gridbar(gen);
  }
}

// FC GEMM bf16 WMMA: logits = h @ fcW^T + fcb
__global__ __launch_bounds__(128) void fc_kernel(const float* __restrict__ bias,
                                                 float* __restrict__ out){
  __shared__ __nv_bfloat16 As[64][48];
  __shared__ __nv_bfloat16 Bs[64][48];
  __shared__ float Cs[64][68];
  int bn = blockIdx.x, bm = blockIdx.y;
  int tid = threadIdx.x;
  int warp = tid >> 5;
  int wm = warp >> 1, wn = warp & 1;
  wmma::fragment<wmma::accumulator,16,16,16,float> acc[2][2];
  #pragma unroll
  for (int i = 0; i < 2; i++)
    #pragma unroll
    for (int j = 0; j < 2; j++) wmma::fill_fragment(acc[i][j], 0.f);

  for (int k0 = 0; k0 < 256; k0 += 32){
    __syncthreads();
    for (int i = tid; i < 256; i += 128){
      int r = i >> 2, cc = (i & 3)*8;
      *(uint4*)&As[r][cc] = *(const uint4*)&g_hb[(size_t)(bm*64+r)*256 + k0 + cc];
      *(uint4*)&Bs[r][cc] = *(const uint4*)&g_wb[(size_t)(bn*64+r)*256 + k0 + cc];
    }
    __syncthreads();
    #pragma unroll
    for (int kk = 0; kk < 2; kk++){
      wmma::fragment<wmma::matrix_a,16,16,16,__nv_bfloat16,wmma::row_major> af[2];
      wmma::fragment<wmma::matrix_b,16,16,16,__nv_bfloat16,wmma::col_major> bf[2];
      #pragma unroll
      for (int i = 0; i < 2; i++) wmma::load_matrix_sync(af[i], &As[wm*32+i*16][kk*16], 48);
      #pragma unroll
      for (int j = 0; j < 2; j++) wmma::load_matrix_sync(bf[j], &Bs[wn*32+j*16][kk*16], 48);
      #pragma unroll
      for (int i = 0; i < 2; i++)
        #pragma unroll
        for (int j = 0; j < 2; j++)
          wmma::mma_sync(acc[i][j], af[i], bf[j], acc[i][j]);
    }
  }
  __syncthreads();
  #pragma unroll
  for (int i = 0; i < 2; i++)
    #pragma unroll
    for (int j = 0; j < 2; j++)
      wmma::store_matrix_sync(&Cs[wm*32+i*16][wn*32+j*16], acc[i][j], 68, wmma::mem_row_major);
  __syncthreads();

  for (int i = tid; i < 1024; i += 128){
    int r = i >> 4, cc = (i & 15)*4;
    int m = bm*64 + r;
    int orow = (m & 15)*Tsz + (m >> 4);
    int n = bn*64 + cc;
    float4 v = *(float4*)&Cs[r][cc];
    v.x += bias[n]; v.y += bias[n+1]; v.z += bias[n+2]; v.w += bias[n+3];
    *(float4*)&out[(size_t)orow*Vsz + n] = v;
  }
}

// in-place log_softmax, one row per block, row cached in dyn smem
__global__ __launch_bounds__(256) void lsm_kernel(float* __restrict__ out){
  extern __shared__ float row[];
  __shared__ float red[8];
  float4* p4 = (float4*)(out + (size_t)blockIdx.x*Vsz);
  float4* r4 = (float4*)row;
  int tid = threadIdx.x;
  float m = -3.4e38f;
  for (int i = tid; i < Vsz/4; i += 256){
    float4 v = p4[i]; r4[i] = v;
    m = fmaxf(m, fmaxf(fmaxf(v.x, v.y), fmaxf(v.z, v.w)));
  }
  #pragma unroll
  for (int o = 16; o; o >>= 1) m = fmaxf(m, __shfl_xor_sync(0xffffffffu, m, o));
  if ((tid & 31) == 0) red[tid >> 5] = m;
  __syncthreads();
  float mm = red[0];
  #pragma unroll
  for (int w = 1; w < 8; w++) mm = fmaxf(mm, red[w]);
  __syncthreads();
  float s = 0.f;
  for (int i = tid; i < Vsz/4; i += 256){
    float4 v = r4[i];
    s += __expf(v.x-mm) + __expf(v.y-mm) + __expf(v.z-mm) + __expf(v.w-mm);
  }
  #pragma unroll
  for (int o = 16; o; o >>= 1) s += __shfl_xor_sync(0xffffffffu, s, o);
  if ((tid & 31) == 0) red[tid >> 5] = s;
  __syncthreads();
  float lse = mm + logf(red[0]+red[1]+red[2]+red[3]+red[4]+red[5]+red[6]+red[7]);
  for (int i = tid; i < Vsz/4; i += 256){
    float4 v = r4[i];
    v.x -= lse; v.y -= lse; v.z -= lse; v.w -= lse;
    p4[i] = v;
  }
}

extern "C" void kernel_launch(void* const* d_in, const int* in_sizes, int n_in,
                              void* d_out, int out_size) {
  const int*   x    = (const int*)  d_in[0];
  const float* emb  = (const float*)d_in[1];
  const float* Wi0  = (const float*)d_in[2];
  const float* Wh0  = (const float*)d_in[3];
  const float* b0   = (const float*)d_in[4];
  const float* Wi1  = (const float*)d_in[5];
  const float* Wh1  = (const float*)d_in[6];
  const float* b1   = (const float*)d_in[7];
  const float* Wi2  = (const float*)d_in[8];
  const float* Wh2  = (const float*)d_in[9];
  const float* b2   = (const float*)d_in[10];
  const float* fcW  = (const float*)d_in[11];
  const float* fcb  = (const float*)d_in[12];
  float* out = (float*)d_out;

  static int lsm_cfg = 0;
  if (!lsm_cfg){
    cudaFuncSetAttribute(lsm_kernel, cudaFuncAttributeMaxDynamicSharedMemorySize, Vsz*4);
    lsm_cfg = 1;
  }

  embed_kernel<<<Msz, 256>>>(x, emb);
  padwi0_kernel<<<G4, 256>>>(Wi0);
  convwb_kernel<<<Vsz, 256>>>(fcW);

  dim3 xg(16, 64);
  xproj_kernel<<<xg, 256>>>(0, Wi0, b0);
  scan_kernel<<<64, 128>>>(Wh0);
  xproj_kernel<<<xg, 256>>>(1, Wi1, b1);
  scan_kernel<<<64, 128>>>(Wh1);
  xproj_kernel<<<xg, 256>>>(1, Wi2, b2);
  scan_kernel<<<64, 128>>>(Wh2);

  convhb_kernel<<<Msz, 256>>>();
  dim3 fg(Vsz/64, Msz/64);
  fc_kernel<<<fg, 128>>>(fcb, out);
  lsm_kernel<<<Msz, 256, Vsz*4>>>(out);
}

// round 5
// speedup vs baseline: 1.7729x; 1.7729x over previous
#include <cuda_runtime.h>
#include <cuda_bf16.h>
#include <mma.h>
#include <cstdint>
using namespace nvcuda;
typedef unsigned long long ull;
typedef unsigned int u32;

#define Bsz 16
#define Tsz 256
#define Esz 200
#define Hsz 256
#define Vsz 32000
#define G4  1024
#define Msz 4096   // B*T rows, time-major: r = t*16 + b

__device__ float g_x[Msz*Hsz];
__device__ float g_xg[Msz*G4];
__device__ float g_hall[Msz*Hsz];
__device__ float g_wi0p[G4*Hsz];
__device__ __nv_bfloat16 g_hb[Msz*Hsz];
__device__ __nv_bfloat16 g_wb[(size_t)Vsz*Hsz];

__device__ __forceinline__ float sigmoidf_(float x){ return 1.f/(1.f+__expf(-x)); }
__device__ __forceinline__ float tanhf_(float x){ return 1.f - 2.f/(__expf(2.f*x)+1.f); }

__device__ __forceinline__ ull pk2(float a, float b){
  ull r; asm("mov.b64 %0,{%1,%2};" : "=l"(r) : "f"(a), "f"(b)); return r;
}
__device__ __forceinline__ void upk2(ull v, float& a, float& b){
  asm("mov.b64 {%0,%1},%2;" : "=f"(a), "=f"(b) : "l"(v));
}
__device__ __forceinline__ ull ffma2(ull a, ull b, ull c){
  ull d; asm("fma.rn.f32x2 %0,%1,%2,%3;" : "=l"(d) : "l"(a), "l"(b), "l"(c)); return d;
}

// ---------------- prep ----------------
__global__ void embed_kernel(const int* __restrict__ x, const float* __restrict__ emb){
  int idx = blockIdx.x*256 + threadIdx.x;
  int r = idx >> 8, k = idx & 255;
  int t = r >> 4, b = r & 15;
  float v = 0.f;
  if (k < Esz) v = emb[(size_t)x[b*Tsz + t]*Esz + k];
  g_x[idx] = v;
}

__global__ void padwi0_kernel(const float* __restrict__ Wi0){
  int idx = blockIdx.x*256 + threadIdx.x;
  int j = idx >> 8, k = idx & 255;
  g_wi0p[idx] = (k < Esz) ? Wi0[j*Esz + k] : 0.f;
}

__global__ void convwb_kernel(const float* __restrict__ fcW){
  size_t idx = (size_t)blockIdx.x*256 + threadIdx.x;
  g_wb[idx] = __float2bfloat16(fcW[idx]);
}

__global__ void convhb_kernel(){
  int idx = blockIdx.x*256 + threadIdx.x;
  g_hb[idx] = __float2bfloat16(g_hall[idx]);
}

// ---------------- input-proj GEMM: g_xg[r][n] = X[r]·W[n] + bias[n] ----------------
__global__ __launch_bounds__(256) void xproj_kernel(int sel,
                                                    const float* __restrict__ Wext,
                                                    const float* __restrict__ bias){
  const float* __restrict__ X = sel ? g_hall : g_x;
  const float* __restrict__ W = sel ? Wext  : g_wi0p;
  __shared__ float As[16][64];
  __shared__ float Bs[16][64];
  int tid = threadIdx.x;
  int tx = tid & 15, ty = tid >> 4;
  int m0 = blockIdx.y*64, n0 = blockIdx.x*64;
  int lr = tid >> 2, lc = (tid & 3)*4;
  float acc[4][4] = {};
  for (int k0 = 0; k0 < 256; k0 += 16){
    float4 xv = *(const float4*)&X[(m0+lr)*256 + k0 + lc];
    float4 wv = *(const float4*)&W[(n0+lr)*256 + k0 + lc];
    __syncthreads();
    As[lc][lr]=xv.x; As[lc+1][lr]=xv.y; As[lc+2][lr]=xv.z; As[lc+3][lr]=xv.w;
    Bs[lc][lr]=wv.x; Bs[lc+1][lr]=wv.y; Bs[lc+2][lr]=wv.z; Bs[lc+3][lr]=wv.w;
    __syncthreads();
    #pragma unroll
    for (int k = 0; k < 16; k++){
      float4 a = *(float4*)&As[k][ty*4];
      float4 b = *(float4*)&Bs[k][tx*4];
      acc[0][0]+=a.x*b.x; acc[0][1]+=a.x*b.y; acc[0][2]+=a.x*b.z; acc[0][3]+=a.x*b.w;
      acc[1][0]+=a.y*b.x; acc[1][1]+=a.y*b.y; acc[1][2]+=a.y*b.z; acc[1][3]+=a.y*b.w;
      acc[2][0]+=a.z*b.x; acc[2][1]+=a.z*b.y; acc[2][2]+=a.z*b.z; acc[2][3]+=a.z*b.w;
      acc[3][0]+=a.w*b.x; acc[3][1]+=a.w*b.y; acc[3][2]+=a.w*b.z; acc[3][3]+=a.w*b.w;
    }
  }
  #pragma unroll
  for (int i = 0; i < 4; i++){
    int mrow = m0 + ty*4 + i;
    #pragma unroll
    for (int j = 0; j < 4; j++){
      int n = n0 + tx*4 + j;
      g_xg[mrow*G4 + n] = acc[i][j] + bias[n];
    }
  }
}

// ---------------- LSTM scan: 1 cluster of 8 CTAs per batch, Wh in registers ----------------
__global__ void __launch_bounds__(512,1) __cluster_dims__(8,1,1)
scan_kernel(const float* __restrict__ Wh){
  __shared__ __align__(16) float hs[2][256];   // ping-pong replicated h
  int tid = threadIdx.x;
  int w = tid >> 5, l = tid & 31;
  int g4 = l >> 3, kl = l & 7;
  u32 rank; asm("mov.u32 %0, %%cluster_ctarank;" : "=r"(rank));
  int b = blockIdx.x >> 3;
  int j = (int)rank;

  // register-resident weights: 2 gate-rows x 8 chunks x 2 f32x2
  ull wgt[2][8][2];
  #pragma unroll
  for (int r = 0; r < 2; r++){
    int rg = 2*g4 + r;             // 0..7
    int u = rg >> 2, gate = rg & 3;
    int n = 32*j + 2*w + u;
    const float4* Wr = (const float4*)(Wh + (gate*256 + n)*256);
    #pragma unroll
    for (int m = 0; m < 8; m++){
      float4 v = Wr[kl + 8*m];
      wgt[r][m][0] = pk2(v.x, v.y);
      wgt[r][m][1] = pk2(v.z, v.w);
    }
  }
  if (tid < 256) hs[0][tid] = 0.f;

  u32 hbase;
  asm("{.reg .u64 t; cvta.to.shared.u64 t,%1; cvt.u32.u64 %0,t;}" : "=r"(hbase) : "l"(&hs[0][0]));

  bool act = ((l & 15) == 0);      // lanes 0 and 16
  int u_loc = l >> 4;
  int n_act = 32*j + 2*w + u_loc;
  float creg = 0.f;
  float xgc[4] = {0.f,0.f,0.f,0.f};
  if (act){
    #pragma unroll
    for (int g = 0; g < 4; g++)
      xgc[g] = __ldg(&g_xg[b*G4 + g*256 + n_act]);   // t=0
  }

  asm volatile("barrier.cluster.arrive.aligned;" ::: "memory");
  asm volatile("barrier.cluster.wait.aligned;" ::: "memory");

  for (int t = 0; t < 256; t++){
    float xgn[4] = {0.f,0.f,0.f,0.f};
    if (act && t < 255){
      #pragma unroll
      for (int g = 0; g < 4; g++)
        xgn[g] = __ldg(&g_xg[((t+1)*16+b)*G4 + g*256 + n_act]);
    }
    u32 rb = hbase + (u32)(t & 1)*1024u;
    ull a0 = 0ull, a1 = 0ull;
    #pragma unroll
    for (int m = 0; m < 8; m++){
      ull h0, h1;
      asm("ld.shared.v2.u64 {%0,%1},[%2];" : "=l"(h0), "=l"(h1)
          : "r"(rb + (u32)(kl + 8*m)*16u));
      a0 = ffma2(wgt[0][m][0], h0, a0);
      a0 = ffma2(wgt[0][m][1], h1, a0);
      a1 = ffma2(wgt[1][m][0], h0, a1);
      a1 = ffma2(wgt[1][m][1], h1, a1);
    }
    float s0, s1, lo, hi;
    upk2(a0, lo, hi); s0 = lo + hi;
    upk2(a1, lo, hi); s1 = lo + hi;
    #pragma unroll
    for (int off = 1; off < 8; off <<= 1){
      s0 += __shfl_xor_sync(0xffffffffu, s0, off);
      s1 += __shfl_xor_sync(0xffffffffu, s1, off);
    }
    float gg = __shfl_xor_sync(0xffffffffu, s0, 8);  // partner group's gate g
    float go = __shfl_xor_sync(0xffffffffu, s1, 8);  // partner group's gate o
    if (act){
      float gi = s0 + xgc[0];
      float gf = s1 + xgc[1];
      float gG = gg + xgc[2];
      float gO = go + xgc[3];
      float iv = sigmoidf_(gi), fv = sigmoidf_(gf);
      float cv = tanhf_(gG),   ov = sigmoidf_(gO);
      creg = fv*creg + iv*cv;
      float hv = ov*tanhf_(creg);
      u32 ha = hbase + (u32)((t+1) & 1)*1024u + (u32)n_act*4u;
      #pragma unroll
      for (int p = 0; p < 8; p++){
        u32 ra;
        asm("mapa.shared::cluster.u32 %0,%1,%2;" : "=r"(ra) : "r"(ha), "r"(p));
        asm volatile("st.shared::cluster.f32 [%0],%1;" :: "r"(ra), "f"(hv) : "memory");
      }
      g_hall[(t*16+b)*256 + n_act] = hv;
      xgc[0]=xgn[0]; xgc[1]=xgn[1]; xgc[2]=xgn[2]; xgc[3]=xgn[3];
    }
    asm volatile("barrier.cluster.arrive.aligned;" ::: "memory");
    asm volatile("barrier.cluster.wait.aligned;" ::: "memory");
  }
}

// ---------------- FC GEMM bf16 WMMA 128x128 tiles ----------------
__global__ __launch_bounds__(256) void fc_kernel(const float* __restrict__ bias,
                                                 float* __restrict__ out){
  __shared__ __nv_bfloat16 As[128][40];
  __shared__ __nv_bfloat16 Bs[128][40];
  __shared__ float stg[8][16][20];
  int bn = blockIdx.x, bm = blockIdx.y;
  int tid = threadIdx.x;
  int warp = tid >> 5, lane = tid & 31;
  int wm = warp >> 2, wn = warp & 3;     // 2 x 4 warps; warp tile 64(M) x 32(N)
  wmma::fragment<wmma::accumulator,16,16,16,float> acc[4][2];
  #pragma unroll
  for (int i = 0; i < 4; i++)
    #pragma unroll
    for (int jj = 0; jj < 2; jj++) wmma::fill_fragment(acc[i][jj], 0.f);

  for (int k0 = 0; k0 < 256; k0 += 32){
    __syncthreads();
    #pragma unroll
    for (int i = tid; i < 512; i += 256){
      int r = i >> 2, c8 = (i & 3)*8;
      *(uint4*)&As[r][c8] = *(const uint4*)&g_hb[(size_t)(bm*128+r)*256 + k0 + c8];
      *(uint4*)&Bs[r][c8] = *(const uint4*)&g_wb[(size_t)(bn*128+r)*256 + k0 + c8];
    }
    __syncthreads();
    #pragma unroll
    for (int kk = 0; kk < 2; kk++){
      wmma::fragment<wmma::matrix_a,16,16,16,__nv_bfloat16,wmma::row_major> af[4];
      wmma::fragment<wmma::matrix_b,16,16,16,__nv_bfloat16,wmma::col_major> bf[2];
      #pragma unroll
      for (int i = 0; i < 4; i++) wmma::load_matrix_sync(af[i], &As[wm*64+i*16][kk*16], 40);
      #pragma unroll
      for (int jj = 0; jj < 2; jj++) wmma::load_matrix_sync(bf[jj], &Bs[wn*32+jj*16][kk*16], 40);
      #pragma unroll
      for (int i = 0; i < 4; i++)
        #pragma unroll
        for (int jj = 0; jj < 2; jj++)
          wmma::mma_sync(acc[i][jj], af[i], bf[jj], acc[i][jj]);
    }
  }

  int er = lane >> 1, ec = (lane & 1)*8;
  #pragma unroll
  for (int i = 0; i < 4; i++){
    #pragma unroll
    for (int jj = 0; jj < 2; jj++){
      wmma::store_matrix_sync(&stg[warp][0][0], acc[i][jj], 20, wmma::mem_row_major);
      __syncwarp();
      int mm = bm*128 + wm*64 + i*16 + er;
      int n0 = bn*128 + wn*32 + jj*16 + ec;
      int orow = (mm & 15)*Tsz + (mm >> 4);
      float4 v0 = *(float4*)&stg[warp][er][ec];
      float4 v1 = *(float4*)&stg[warp][er][ec+4];
      v0.x += bias[n0];   v0.y += bias[n0+1]; v0.z += bias[n0+2]; v0.w += bias[n0+3];
      v1.x += bias[n0+4]; v1.y += bias[n0+5]; v1.z += bias[n0+6]; v1.w += bias[n0+7];
      *(float4*)&out[(size_t)orow*Vsz + n0]     = v0;
      *(float4*)&out[(size_t)orow*Vsz + n0 + 4] = v1;
      __syncwarp();
    }
  }
}

// ---------------- in-place log_softmax ----------------
__global__ __launch_bounds__(1024) void lsm_kernel(float* __restrict__ out){
  extern __shared__ float row[];
  __shared__ float red[32];
  float4* p4 = (float4*)(out + (size_t)blockIdx.x*Vsz);
  float4* r4 = (float4*)row;
  int tid = threadIdx.x;
  float m = -3.4e38f;
  for (int i = tid; i < Vsz/4; i += 1024){
    float4 v = p4[i]; r4[i] = v;
    m = fmaxf(m, fmaxf(fmaxf(v.x, v.y), fmaxf(v.z, v.w)));
  }
  #pragma unroll
  for (int o = 16; o; o >>= 1) m = fmaxf(m, __shfl_xor_sync(0xffffffffu, m, o));
  if ((tid & 31) == 0) red[tid >> 5] = m;
  __syncthreads();
  float mm = red[0];
  #pragma unroll
  for (int ww = 1; ww < 32; ww++) mm = fmaxf(mm, red[ww]);
  __syncthreads();
  float s = 0.f;
  for (int i = tid; i < Vsz/4; i += 1024){
    float4 v = r4[i];
    s += __expf(v.x-mm) + __expf(v.y-mm) + __expf(v.z-mm) + __expf(v.w-mm);
  }
  #pragma unroll
  for (int o = 16; o; o >>= 1) s += __shfl_xor_sync(0xffffffffu, s, o);
  if ((tid & 31) == 0) red[tid >> 5] = s;
  __syncthreads();
  float ss = 0.f;
  #pragma unroll
  for (int ww = 0; ww < 32; ww++) ss += red[ww];
  float lse = mm + logf(ss);
  for (int i = tid; i < Vsz/4; i += 1024){
    float4 v = r4[i];
    v.x -= lse; v.y -= lse; v.z -= lse; v.w -= lse;
    p4[i] = v;
  }
}

extern "C" void kernel_launch(void* const* d_in, const int* in_sizes, int n_in,
                              void* d_out, int out_size) {
  const int*   x    = (const int*)  d_in[0];
  const float* emb  = (const float*)d_in[1];
  const float* Wi0  = (const float*)d_in[2];
  const float* Wh0  = (const float*)d_in[3];
  const float* b0   = (const float*)d_in[4];
  const float* Wi1  = (const float*)d_in[5];
  const float* Wh1  = (const float*)d_in[6];
  const float* b1   = (const float*)d_in[7];
  const float* Wi2  = (const float*)d_in[8];
  const float* Wh2  = (const float*)d_in[9];
  const float* b2   = (const float*)d_in[10];
  const float* fcW  = (const float*)d_in[11];
  const float* fcb  = (const float*)d_in[12];
  float* out = (float*)d_out;

  static int cfg = 0;
  if (!cfg){
    cudaFuncSetAttribute(lsm_kernel, cudaFuncAttributeMaxDynamicSharedMemorySize, Vsz*4);
    cfg = 1;
  }

  embed_kernel<<<Msz, 256>>>(x, emb);
  padwi0_kernel<<<G4, 256>>>(Wi0);
  convwb_kernel<<<Vsz, 256>>>(fcW);

  dim3 xg(16, 64);
  xproj_kernel<<<xg, 256>>>(0, Wi0, b0);
  scan_kernel<<<128, 512>>>(Wh0);
  xproj_kernel<<<xg, 256>>>(1, Wi1, b1);
  scan_kernel<<<128, 512>>>(Wh1);
  xproj_kernel<<<xg, 256>>>(1, Wi2, b2);
  scan_kernel<<<128, 512>>>(Wh2);

  convhb_kernel<<<Msz, 256>>>();
  dim3 fg(Vsz/128, Msz/128);
  fc_kernel<<<fg, 256>>>(fcb, out);
  lsm_kernel<<<Msz, 1024, Vsz*4>>>(out);
}

// round 6
// speedup vs baseline: 1.9367x; 1.0923x over previous
#include <cuda_runtime.h>
#include <cuda_bf16.h>
#include <mma.h>
#include <cstdint>
using namespace nvcuda;
typedef unsigned long long ull;
typedef unsigned int u32;

#define Bsz 16
#define Tsz 256
#define Esz 200
#define Hsz 256
#define Vsz 32000
#define G4  1024
#define Msz 4096   // B*T rows, time-major: r = t*16 + b

__device__ float g_x[Msz*Hsz];
__device__ float g_xg[Msz*G4];
__device__ float g_hall[Msz*Hsz];
__device__ float g_wi0p[G4*Hsz];
__device__ __nv_bfloat16 g_hb[Msz*Hsz];
__device__ __nv_bfloat16 g_wb[(size_t)Vsz*Hsz];

__device__ __forceinline__ float sigmoidf_(float x){ return 1.f/(1.f+__expf(-x)); }
__device__ __forceinline__ float tanhf_(float x){ return 1.f - 2.f/(__expf(2.f*x)+1.f); }

__device__ __forceinline__ ull pk2(float a, float b){
  ull r; asm("mov.b64 %0,{%1,%2};" : "=l"(r) : "f"(a), "f"(b)); return r;
}
__device__ __forceinline__ void upk2(ull v, float& a, float& b){
  asm("mov.b64 {%0,%1},%2;" : "=f"(a), "=f"(b) : "l"(v));
}
__device__ __forceinline__ ull ffma2(ull a, ull b, ull c){
  ull d; asm("fma.rn.f32x2 %0,%1,%2,%3;" : "=l"(d) : "l"(a), "l"(b), "l"(c)); return d;
}

// ---------------- prep ----------------
__global__ void embed_kernel(const int* __restrict__ x, const float* __restrict__ emb){
  int idx = blockIdx.x*256 + threadIdx.x;
  int r = idx >> 8, k = idx & 255;
  int t = r >> 4, b = r & 15;
  float v = 0.f;
  if (k < Esz) v = emb[(size_t)x[b*Tsz + t]*Esz + k];
  g_x[idx] = v;
}

__global__ void padwi0_kernel(const float* __restrict__ Wi0){
  int idx = blockIdx.x*256 + threadIdx.x;
  int j = idx >> 8, k = idx & 255;
  g_wi0p[idx] = (k < Esz) ? Wi0[j*Esz + k] : 0.f;
}

__global__ void convwb_kernel(const float* __restrict__ fcW){
  size_t idx = (size_t)blockIdx.x*256 + threadIdx.x;
  g_wb[idx] = __float2bfloat16(fcW[idx]);
}

__global__ void convhb_kernel(){
  int idx = blockIdx.x*256 + threadIdx.x;
  g_hb[idx] = __float2bfloat16(g_hall[idx]);
}

// ---------------- input-proj GEMM: g_xg[r][n] = X[r]·W[n] + bias[n] ----------------
__global__ __launch_bounds__(256) void xproj_kernel(int sel,
                                                    const float* __restrict__ Wext,
                                                    const float* __restrict__ bias){
  const float* __restrict__ X = sel ? g_hall : g_x;
  const float* __restrict__ W = sel ? Wext  : g_wi0p;
  __shared__ float As[16][64];
  __shared__ float Bs[16][64];
  int tid = threadIdx.x;
  int tx = tid & 15, ty = tid >> 4;
  int m0 = blockIdx.y*64, n0 = blockIdx.x*64;
  int lr = tid >> 2, lc = (tid & 3)*4;
  float acc[4][4] = {};
  for (int k0 = 0; k0 < 256; k0 += 16){
    float4 xv = *(const float4*)&X[(m0+lr)*256 + k0 + lc];
    float4 wv = *(const float4*)&W[(n0+lr)*256 + k0 + lc];
    __syncthreads();
    As[lc][lr]=xv.x; As[lc+1][lr]=xv.y; As[lc+2][lr]=xv.z; As[lc+3][lr]=xv.w;
    Bs[lc][lr]=wv.x; Bs[lc+1][lr]=wv.y; Bs[lc+2][lr]=wv.z; Bs[lc+3][lr]=wv.w;
    __syncthreads();
    #pragma unroll
    for (int k = 0; k < 16; k++){
      float4 a = *(float4*)&As[k][ty*4];
      float4 b = *(float4*)&Bs[k][tx*4];
      acc[0][0]+=a.x*b.x; acc[0][1]+=a.x*b.y; acc[0][2]+=a.x*b.z; acc[0][3]+=a.x*b.w;
      acc[1][0]+=a.y*b.x; acc[1][1]+=a.y*b.y; acc[1][2]+=a.y*b.z; acc[1][3]+=a.y*b.w;
      acc[2][0]+=a.z*b.x; acc[2][1]+=a.z*b.y; acc[2][2]+=a.z*b.z; acc[2][3]+=a.z*b.w;
      acc[3][0]+=a.w*b.x; acc[3][1]+=a.w*b.y; acc[3][2]+=a.w*b.z; acc[3][3]+=a.w*b.w;
    }
  }
  #pragma unroll
  for (int i = 0; i < 4; i++){
    int mrow = m0 + ty*4 + i;
    #pragma unroll
    for (int j = 0; j < 4; j++){
      int n = n0 + tx*4 + j;
      g_xg[mrow*G4 + n] = acc[i][j] + bias[n];
    }
  }
}

// ---------------- LSTM scan: 1 cluster of 8 CTAs per batch, Wh in registers ----------------
__global__ void __launch_bounds__(512,1) __cluster_dims__(8,1,1)
scan_kernel(const float* __restrict__ Wh){
  __shared__ __align__(16) float hs[2][256];   // ping-pong replicated h
  int tid = threadIdx.x;
  int w = tid >> 5, l = tid & 31;
  int g4 = l >> 3, kl = l & 7;
  u32 rank; asm("mov.u32 %0, %%cluster_ctarank;" : "=r"(rank));
  int b = blockIdx.x >> 3;
  int j = (int)rank;

  // register-resident weights: 2 gate-rows x 8 chunks x 2 f32x2
  ull wgt[2][8][2];
  #pragma unroll
  for (int r = 0; r < 2; r++){
    int rg = 2*g4 + r;             // 0..7
    int u = rg >> 2, gate = rg & 3;
    int n = 32*j + 2*w + u;
    const float4* Wr = (const float4*)(Wh + (gate*256 + n)*256);
    #pragma unroll
    for (int m = 0; m < 8; m++){
      float4 v = Wr[kl + 8*m];
      wgt[r][m][0] = pk2(v.x, v.y);
      wgt[r][m][1] = pk2(v.z, v.w);
    }
  }
  if (tid < 256) hs[0][tid] = 0.f;

  u32 hbase;
  asm("{.reg .u64 t; cvta.to.shared.u64 t,%1; cvt.u32.u64 %0,t;}" : "=r"(hbase) : "l"(&hs[0][0]));

  bool act = ((l & 15) == 0);      // lanes 0 and 16
  int u_loc = l >> 4;
  int n_act = 32*j + 2*w + u_loc;
  float creg = 0.f;
  float xgc[4] = {0.f,0.f,0.f,0.f};
  float xgn[4] = {0.f,0.f,0.f,0.f};
  if (act){
    #pragma unroll
    for (int g = 0; g < 4; g++){
      xgc[g] = __ldg(&g_xg[(0*16+b)*G4 + g*256 + n_act]);
      xgn[g] = __ldg(&g_xg[(1*16+b)*G4 + g*256 + n_act]);
    }
  }

  asm volatile("barrier.cluster.arrive.aligned;" ::: "memory");
  asm volatile("barrier.cluster.wait.aligned;" ::: "memory");

  for (int t = 0; t < 256; t++){
    u32 rb = hbase + (u32)(t & 1)*1024u;
    ull a0 = 0ull, a1 = 0ull;
    #pragma unroll
    for (int m = 0; m < 8; m++){
      ull h0, h1;
      asm("ld.shared.v2.u64 {%0,%1},[%2];" : "=l"(h0), "=l"(h1)
          : "r"(rb + (u32)(kl + 8*m)*16u));
      a0 = ffma2(wgt[0][m][0], h0, a0);
      a0 = ffma2(wgt[0][m][1], h1, a0);
      a1 = ffma2(wgt[1][m][0], h0, a1);
      a1 = ffma2(wgt[1][m][1], h1, a1);
    }
    float s0, s1, lo, hi;
    upk2(a0, lo, hi); s0 = lo + hi;
    upk2(a1, lo, hi); s1 = lo + hi;
    #pragma unroll
    for (int off = 1; off < 8; off <<= 1){
      s0 += __shfl_xor_sync(0xffffffffu, s0, off);
      s1 += __shfl_xor_sync(0xffffffffu, s1, off);
    }
    float gg = __shfl_xor_sync(0xffffffffu, s0, 8);  // partner group's gate g
    float go = __shfl_xor_sync(0xffffffffu, s1, 8);  // partner group's gate o
    float hv = 0.f;
    if (act){
      float gi = s0 + xgc[0];
      float gf = s1 + xgc[1];
      float gG = gg + xgc[2];
      float gO = go + xgc[3];
      float iv = sigmoidf_(gi), fv = sigmoidf_(gf);
      float cv = tanhf_(gG),   ov = sigmoidf_(gO);
      creg = fv*creg + iv*cv;
      hv = ov*tanhf_(creg);
      u32 ha = hbase + (u32)((t+1) & 1)*1024u + (u32)n_act*4u;
      #pragma unroll
      for (int p = 0; p < 8; p++){
        u32 ra;
        asm("mapa.shared::cluster.u32 %0,%1,%2;" : "=r"(ra) : "r"(ha), "r"(p));
        asm volatile("st.shared::cluster.f32 [%0],%1;" :: "r"(ra), "f"(hv) : "memory");
      }
    }
    asm volatile("barrier.cluster.arrive.aligned;" ::: "memory");
    // hide behind barrier wait: output store + t+2 prefetch
    if (act){
      g_hall[(t*16+b)*256 + n_act] = hv;
      xgc[0]=xgn[0]; xgc[1]=xgn[1]; xgc[2]=xgn[2]; xgc[3]=xgn[3];
      if (t + 2 < 256){
        #pragma unroll
        for (int g = 0; g < 4; g++)
          xgn[g] = __ldg(&g_xg[((t+2)*16+b)*G4 + g*256 + n_act]);
      }
    }
    asm volatile("barrier.cluster.wait.aligned;" ::: "memory");
  }
}

// ---------------- FC GEMM bf16 WMMA, cp.async double-buffered ----------------
__global__ __launch_bounds__(256) void fc_kernel(const float* __restrict__ bias,
                                                 float* __restrict__ out){
  __shared__ __nv_bfloat16 As[2][128][40];
  __shared__ __nv_bfloat16 Bs[2][128][40];
  __shared__ float stg[8][16][20];
  int bn = blockIdx.x, bm = blockIdx.y;
  int tid = threadIdx.x;
  int warp = tid >> 5, lane = tid & 31;
  int wm = warp >> 2, wn = warp & 3;     // 2 x 4 warps; warp tile 64(M) x 32(N)
  const __nv_bfloat16* Ab = g_hb + (size_t)(bm*128)*256;
  const __nv_bfloat16* Bb = g_wb + (size_t)(bn*128)*256;

  int cid0 = tid*2;
  int r0 = cid0 >> 2,      c80 = (cid0 & 3)*8;
  int r1 = (cid0+1) >> 2,  c81 = ((cid0+1) & 3)*8;

  wmma::fragment<wmma::accumulator,16,16,16,float> acc[4][2];
  #pragma unroll
  for (int i = 0; i < 4; i++)
    #pragma unroll
    for (int jj = 0; jj < 2; jj++) wmma::fill_fragment(acc[i][jj], 0.f);

  #define FC_ISSUE(stage, c)                                                     \
    {                                                                            \
      int k0_ = (c)*32;                                                          \
      u32 sa0 = (u32)__cvta_generic_to_shared(&As[stage][r0][c80]);              \
      u32 sb0 = (u32)__cvta_generic_to_shared(&Bs[stage][r0][c80]);              \
      u32 sa1 = (u32)__cvta_generic_to_shared(&As[stage][r1][c81]);              \
      u32 sb1 = (u32)__cvta_generic_to_shared(&Bs[stage][r1][c81]);              \
      asm volatile("cp.async.cg.shared.global [%0],[%1],16;\n"                   \
                   :: "r"(sa0), "l"(Ab + (size_t)r0*256 + k0_ + c80));           \
      asm volatile("cp.async.cg.shared.global [%0],[%1],16;\n"                   \
                   :: "r"(sb0), "l"(Bb + (size_t)r0*256 + k0_ + c80));           \
      asm volatile("cp.async.cg.shared.global [%0],[%1],16;\n"                   \
                   :: "r"(sa1), "l"(Ab + (size_t)r1*256 + k0_ + c81));           \
      asm volatile("cp.async.cg.shared.global [%0],[%1],16;\n"                   \
                   :: "r"(sb1), "l"(Bb + (size_t)r1*256 + k0_ + c81));           \
      asm volatile("cp.async.commit_group;\n");                                  \
    }

  FC_ISSUE(0, 0)
  FC_ISSUE(1, 1)

  for (int c = 0; c < 8; c++){
    int s = c & 1;
    asm volatile("cp.async.wait_group 1;\n" ::: "memory");
    __syncthreads();
    wmma::fragment<wmma::matrix_a,16,16,16,__nv_bfloat16,wmma::row_major> af[2][4];
    wmma::fragment<wmma::matrix_b,16,16,16,__nv_bfloat16,wmma::col_major> bf[2][2];
    #pragma unroll
    for (int kk = 0; kk < 2; kk++){
      #pragma unroll
      for (int i = 0; i < 4; i++) wmma::load_matrix_sync(af[kk][i], &As[s][wm*64+i*16][kk*16], 40);
      #pragma unroll
      for (int jj = 0; jj < 2; jj++) wmma::load_matrix_sync(bf[kk][jj], &Bs[s][wn*32+jj*16][kk*16], 40);
    }
    __syncthreads();
    if (c + 2 < 8) FC_ISSUE(s, c+2)
    #pragma unroll
    for (int kk = 0; kk < 2; kk++)
      #pragma unroll
      for (int i = 0; i < 4; i++)
        #pragma unroll
        for (int jj = 0; jj < 2; jj++)
          wmma::mma_sync(acc[i][jj], af[kk][i], bf[kk][jj], acc[i][jj]);
  }
  #undef FC_ISSUE

  int er = lane >> 1, ec = (lane & 1)*8;
  #pragma unroll
  for (int i = 0; i < 4; i++){
    #pragma unroll
    for (int jj = 0; jj < 2; jj++){
      wmma::store_matrix_sync(&stg[warp][0][0], acc[i][jj], 20, wmma::mem_row_major);
      __syncwarp();
      int mm = bm*128 + wm*64 + i*16 + er;
      int n0 = bn*128 + wn*32 + jj*16 + ec;
      int orow = (mm & 15)*Tsz + (mm >> 4);
      float4 v0 = *(float4*)&stg[warp][er][ec];
      float4 v1 = *(float4*)&stg[warp][er][ec+4];
      v0.x += bias[n0];   v0.y += bias[n0+1]; v0.z += bias[n0+2]; v0.w += bias[n0+3];
      v1.x += bias[n0+4]; v1.y += bias[n0+5]; v1.z += bias[n0+6]; v1.w += bias[n0+7];
      *(float4*)&out[(size_t)orow*Vsz + n0]     = v0;
      *(float4*)&out[(size_t)orow*Vsz + n0 + 4] = v1;
      __syncwarp();
    }
  }
}

// ---------------- in-place log_softmax, row register-resident ----------------
__global__ __launch_bounds__(1024) void lsm_kernel(float* __restrict__ out){
  __shared__ float red[32];
  float4* p4 = (float4*)(out + (size_t)blockIdx.x*Vsz);
  int tid = threadIdx.x;
  float4 v[8];
  float m = -3.4e38f;
  #pragma unroll
  for (int i = 0; i < 8; i++){
    int idx = tid + i*1024;
    if (idx < Vsz/4){
      v[i] = p4[idx];
      m = fmaxf(m, fmaxf(fmaxf(v[i].x, v[i].y), fmaxf(v[i].z, v[i].w)));
    }
  }
  #pragma unroll
  for (int o = 16; o; o >>= 1) m = fmaxf(m, __shfl_xor_sync(0xffffffffu, m, o));
  if ((tid & 31) == 0) red[tid >> 5] = m;
  __syncthreads();
  float mm = red[0];
  #pragma unroll
  for (int ww = 1; ww < 32; ww++) mm = fmaxf(mm, red[ww]);
  __syncthreads();
  float s = 0.f;
  #pragma unroll
  for (int i = 0; i < 8; i++){
    int idx = tid + i*1024;
    if (idx < Vsz/4)
      s += __expf(v[i].x-mm) + __expf(v[i].y-mm) + __expf(v[i].z-mm) + __expf(v[i].w-mm);
  }
  #pragma unroll
  for (int o = 16; o; o >>= 1) s += __shfl_xor_sync(0xffffffffu, s, o);
  if ((tid & 31) == 0) red[tid >> 5] = s;
  __syncthreads();
  float ss = 0.f;
  #pragma unroll
  for (int ww = 0; ww < 32; ww++) ss += red[ww];
  float lse = mm + logf(ss);
  #pragma unroll
  for (int i = 0; i < 8; i++){
    int idx = tid + i*1024;
    if (idx < Vsz/4){
      float4 o4 = v[i];
      o4.x -= lse; o4.y -= lse; o4.z -= lse; o4.w -= lse;
      p4[idx] = o4;
    }
  }
}

extern "C" void kernel_launch(void* const* d_in, const int* in_sizes, int n_in,
                              void* d_out, int out_size) {
  const int*   x    = (const int*)  d_in[0];
  const float* emb  = (const float*)d_in[1];
  const float* Wi0  = (const float*)d_in[2];
  const float* Wh0  = (const float*)d_in[3];
  const float* b0   = (const float*)d_in[4];
  const float* Wi1  = (const float*)d_in[5];
  const float* Wh1  = (const float*)d_in[6];
  const float* b1   = (const float*)d_in[7];
  const float* Wi2  = (const float*)d_in[8];
  const float* Wh2  = (const float*)d_in[9];
  const float* b2   = (const float*)d_in[10];
  const float* fcW  = (const float*)d_in[11];
  const float* fcb  = (const float*)d_in[12];
  float* out = (float*)d_out;

  embed_kernel<<<Msz, 256>>>(x, emb);
  padwi0_kernel<<<G4, 256>>>(Wi0);
  convwb_kernel<<<Vsz, 256>>>(fcW);

  dim3 xg(16, 64);
  xproj_kernel<<<xg, 256>>>(0, Wi0, b0);
  scan_kernel<<<128, 512>>>(Wh0);
  xproj_kernel<<<xg, 256>>>(1, Wi1, b1);
  scan_kernel<<<128, 512>>>(Wh1);
  xproj_kernel<<<xg, 256>>>(1, Wi2, b2);
  scan_kernel<<<128, 512>>>(Wh2);

  convhb_kernel<<<Msz, 256>>>();
  dim3 fg(Vsz/128, Msz/128);
  fc_kernel<<<fg, 256>>>(fcb, out);
  lsm_kernel<<<Msz, 1024>>>(out);
}

// round 8
// speedup vs baseline: 1.9393x; 1.0014x over previous
#include <cuda_runtime.h>
#include <cuda_bf16.h>
#include <mma.h>
#include <cstdint>
using namespace nvcuda;
typedef unsigned long long ull;
typedef unsigned int u32;

#define Bsz 16
#define Tsz 256
#define Esz 200
#define Hsz 256
#define Vsz 32000
#define G4  1024
#define Msz 4096   // B*T rows, time-major: r = t*16 + b

__device__ float g_x[Msz*Hsz];
__device__ float g_xg[Msz*G4];
__device__ float g_hall[Msz*Hsz];
__device__ float g_wi0p[G4*Hsz];
__device__ __nv_bfloat16 g_hb[Msz*Hsz];
__device__ __nv_bfloat16 g_wb[(size_t)Vsz*Hsz];

__device__ __forceinline__ float sigmoidf_(float x){ return 1.f/(1.f+__expf(-x)); }
__device__ __forceinline__ float tanhf_(float x){ return 1.f - 2.f/(__expf(2.f*x)+1.f); }

__device__ __forceinline__ ull pk2(float a, float b){
  ull r; asm("mov.b64 %0,{%1,%2};" : "=l"(r) : "f"(a), "f"(b)); return r;
}
__device__ __forceinline__ void upk2(ull v, float& a, float& b){
  asm("mov.b64 {%0,%1},%2;" : "=f"(a), "=f"(b) : "l"(v));
}
__device__ __forceinline__ ull ffma2(ull a, ull b, ull c){
  ull d; asm("fma.rn.f32x2 %0,%1,%2,%3;" : "=l"(d) : "l"(a), "l"(b), "l"(c)); return d;
}

// ---------------- prep ----------------
__global__ void embed_kernel(const int* __restrict__ x, const float* __restrict__ emb){
  int idx = blockIdx.x*256 + threadIdx.x;
  int r = idx >> 8, k = idx & 255;
  int t = r >> 4, b = r & 15;
  float v = 0.f;
  if (k < Esz) v = emb[(size_t)x[b*Tsz + t]*Esz + k];
  g_x[idx] = v;
}

__global__ void padwi0_kernel(const float* __restrict__ Wi0){
  int idx = blockIdx.x*256 + threadIdx.x;
  int j = idx >> 8, k = idx & 255;
  g_wi0p[idx] = (k < Esz) ? Wi0[j*Esz + k] : 0.f;
}

__global__ void convwb_kernel(const float* __restrict__ fcW){
  size_t idx = (size_t)blockIdx.x*256 + threadIdx.x;
  g_wb[idx] = __float2bfloat16(fcW[idx]);
}

// ---------------- input-proj GEMM: g_xg[r][n] = X[r]·W[n] + bias[n] ----------------
__global__ __launch_bounds__(256) void xproj_kernel(int sel,
                                                    const float* __restrict__ Wext,
                                                    const float* __restrict__ bias){
  const float* __restrict__ X = sel ? g_hall : g_x;
  const float* __restrict__ W = sel ? Wext  : g_wi0p;
  __shared__ float As[16][64];
  __shared__ float Bs[16][64];
  int tid = threadIdx.x;
  int tx = tid & 15, ty = tid >> 4;
  int m0 = blockIdx.y*64, n0 = blockIdx.x*64;
  int lr = tid >> 2, lc = (tid & 3)*4;
  float acc[4][4] = {};
  for (int k0 = 0; k0 < 256; k0 += 16){
    float4 xv = *(const float4*)&X[(m0+lr)*256 + k0 + lc];
    float4 wv = *(const float4*)&W[(n0+lr)*256 + k0 + lc];
    __syncthreads();
    As[lc][lr]=xv.x; As[lc+1][lr]=xv.y; As[lc+2][lr]=xv.z; As[lc+3][lr]=xv.w;
    Bs[lc][lr]=wv.x; Bs[lc+1][lr]=wv.y; Bs[lc+2][lr]=wv.z; Bs[lc+3][lr]=wv.w;
    __syncthreads();
    #pragma unroll
    for (int k = 0; k < 16; k++){
      float4 a = *(float4*)&As[k][ty*4];
      float4 b = *(float4*)&Bs[k][tx*4];
      acc[0][0]+=a.x*b.x; acc[0][1]+=a.x*b.y; acc[0][2]+=a.x*b.z; acc[0][3]+=a.x*b.w;
      acc[1][0]+=a.y*b.x; acc[1][1]+=a.y*b.y; acc[1][2]+=a.y*b.z; acc[1][3]+=a.y*b.w;
      acc[2][0]+=a.z*b.x; acc[2][1]+=a.z*b.y; acc[2][2]+=a.z*b.z; acc[2][3]+=a.z*b.w;
      acc[3][0]+=a.w*b.x; acc[3][1]+=a.w*b.y; acc[3][2]+=a.w*b.z; acc[3][3]+=a.w*b.w;
    }
  }
  #pragma unroll
  for (int i = 0; i < 4; i++){
    int mrow = m0 + ty*4 + i;
    #pragma unroll
    for (int j = 0; j < 4; j++){
      int n = n0 + tx*4 + j;
      g_xg[mrow*G4 + n] = acc[i][j] + bias[n];
    }
  }
}

// ---------------- LSTM scan: 1 cluster of 8 CTAs per batch, Wh in registers ----------------
// last==1: write bf16 h into g_hb (final layer) instead of f32 g_hall.
__global__ void __launch_bounds__(512,1) __cluster_dims__(8,1,1)
scan_kernel(const float* __restrict__ Wh, int last){
  __shared__ __align__(16) float hs[2][256];   // ping-pong replicated h
  int tid = threadIdx.x;
  int w = tid >> 5, l = tid & 31;
  int g4 = l >> 3, kl = l & 7;
  u32 rank; asm("mov.u32 %0, %%cluster_ctarank;" : "=r"(rank));
  int b = blockIdx.x >> 3;
  int j = (int)rank;

  // register-resident weights: 2 gate-rows x 8 chunks x 2 f32x2
  ull wgt[2][8][2];
  #pragma unroll
  for (int r = 0; r < 2; r++){
    int rg = 2*g4 + r;             // 0..7
    int u = rg >> 2, gate = rg & 3;
    int n = 32*j + 2*w + u;
    const float4* Wr = (const float4*)(Wh + (gate*256 + n)*256);
    #pragma unroll
    for (int m = 0; m < 8; m++){
      float4 v = Wr[kl + 8*m];
      wgt[r][m][0] = pk2(v.x, v.y);
      wgt[r][m][1] = pk2(v.z, v.w);
    }
  }
  if (tid < 256) hs[0][tid] = 0.f;

  u32 hbase;
  asm("{.reg .u64 t; cvta.to.shared.u64 t,%1; cvt.u32.u64 %0,t;}" : "=r"(hbase) : "l"(&hs[0][0]));

  bool act = ((l & 15) == 0);      // lanes 0 and 16
  int u_loc = l >> 4;
  int n_act = 32*j + 2*w + u_loc;
  float creg = 0.f;
  float xgc[4] = {0.f,0.f,0.f,0.f};
  float xgn[4] = {0.f,0.f,0.f,0.f};
  if (act){
    #pragma unroll
    for (int g = 0; g < 4; g++){
      xgc[g] = __ldg(&g_xg[(0*16+b)*G4 + g*256 + n_act]);
      xgn[g] = __ldg(&g_xg[(1*16+b)*G4 + g*256 + n_act]);
    }
  }

  asm volatile("barrier.cluster.arrive.aligned;" ::: "memory");
  asm volatile("barrier.cluster.wait.aligned;" ::: "memory");

  for (int t = 0; t < 256; t++){
    u32 rb = hbase + (u32)(t & 1)*1024u;
    ull a0 = 0ull, a1 = 0ull;
    #pragma unroll
    for (int m = 0; m < 8; m++){
      ull h0, h1;
      asm("ld.shared.v2.u64 {%0,%1},[%2];" : "=l"(h0), "=l"(h1)
          : "r"(rb + (u32)(kl + 8*m)*16u));
      a0 = ffma2(wgt[0][m][0], h0, a0);
      a0 = ffma2(wgt[0][m][1], h1, a0);
      a1 = ffma2(wgt[1][m][0], h0, a1);
      a1 = ffma2(wgt[1][m][1], h1, a1);
    }
    float s0, s1, lo, hi;
    upk2(a0, lo, hi); s0 = lo + hi;
    upk2(a1, lo, hi); s1 = lo + hi;
    #pragma unroll
    for (int off = 1; off < 8; off <<= 1){
      s0 += __shfl_xor_sync(0xffffffffu, s0, off);
      s1 += __shfl_xor_sync(0xffffffffu, s1, off);
    }
    float gg = __shfl_xor_sync(0xffffffffu, s0, 8);  // partner group's gate g
    float go = __shfl_xor_sync(0xffffffffu, s1, 8);  // partner group's gate o
    float hv = 0.f;
    if (act){
      float gi = s0 + xgc[0];
      float gf = s1 + xgc[1];
      float gG = gg + xgc[2];
      float gO = go + xgc[3];
      float iv = sigmoidf_(gi), fv = sigmoidf_(gf);
      float cv = tanhf_(gG),   ov = sigmoidf_(gO);
      creg = fv*creg + iv*cv;
      hv = ov*tanhf_(creg);
      u32 ha = hbase + (u32)((t+1) & 1)*1024u + (u32)n_act*4u;
      #pragma unroll
      for (int p = 0; p < 8; p++){
        u32 ra;
        asm("mapa.shared::cluster.u32 %0,%1,%2;" : "=r"(ra) : "r"(ha), "r"(p));
        asm volatile("st.shared::cluster.f32 [%0],%1;" :: "r"(ra), "f"(hv) : "memory");
      }
    }
    asm volatile("barrier.cluster.arrive.aligned;" ::: "memory");
    // hidden behind barrier wait: output store + t+2 prefetch
    if (act){
      if (last) g_hb[(t*16+b)*256 + n_act] = __float2bfloat16(hv);
      else      g_hall[(t*16+b)*256 + n_act] = hv;
      xgc[0]=xgn[0]; xgc[1]=xgn[1]; xgc[2]=xgn[2]; xgc[3]=xgn[3];
      if (t + 2 < 256){
        #pragma unroll
        for (int g = 0; g < 4; g++)
          xgn[g] = __ldg(&g_xg[((t+2)*16+b)*G4 + g*256 + n_act]);
      }
    }
    asm volatile("barrier.cluster.wait.aligned;" ::: "memory");
  }
}

// ---------------- FC GEMM bf16 WMMA, cp.async double-buffered ----------------
__global__ __launch_bounds__(256) void fc_kernel(const float* __restrict__ bias,
                                                 float* __restrict__ out){
  __shared__ __nv_bfloat16 As[2][128][40];
  __shared__ __nv_bfloat16 Bs[2][128][40];
  __shared__ float stg[8][16][20];
  int bn = blockIdx.x, bm = blockIdx.y;
  int tid = threadIdx.x;
  int warp = tid >> 5, lane = tid & 31;
  int wm = warp >> 2, wn = warp & 3;     // 2 x 4 warps; warp tile 64(M) x 32(N)
  const __nv_bfloat16* Ab = g_hb + (size_t)(bm*128)*256;
  const __nv_bfloat16* Bb = g_wb + (size_t)(bn*128)*256;

  int cid0 = tid*2;
  int r0 = cid0 >> 2,      c80 = (cid0 & 3)*8;
  int r1 = (cid0+1) >> 2,  c81 = ((cid0+1) & 3)*8;

  wmma::fragment<wmma::accumulator,16,16,16,float> acc[4][2];
  #pragma unroll
  for (int i = 0; i < 4; i++)
    #pragma unroll
    for (int jj = 0; jj < 2; jj++) wmma::fill_fragment(acc[i][jj], 0.f);

  #define FC_ISSUE(stage, c)                                                     \
    {                                                                            \
      int k0_ = (c)*32;                                                          \
      u32 sa0 = (u32)__cvta_generic_to_shared(&As[stage][r0][c80]);              \
      u32 sb0 = (u32)__cvta_generic_to_shared(&Bs[stage][r0][c80]);              \
      u32 sa1 = (u32)__cvta_generic_to_shared(&As[stage][r1][c81]);              \
      u32 sb1 = (u32)__cvta_generic_to_shared(&Bs[stage][r1][c81]);              \
      asm volatile("cp.async.cg.shared.global [%0],[%1],16;\n"                   \
                   :: "r"(sa0), "l"(Ab + (size_t)r0*256 + k0_ + c80));           \
      asm volatile("cp.async.cg.shared.global [%0],[%1],16;\n"                   \
                   :: "r"(sb0), "l"(Bb + (size_t)r0*256 + k0_ + c80));           \
      asm volatile("cp.async.cg.shared.global [%0],[%1],16;\n"                   \
                   :: "r"(sa1), "l"(Ab + (size_t)r1*256 + k0_ + c81));           \
      asm volatile("cp.async.cg.shared.global [%0],[%1],16;\n"                   \
                   :: "r"(sb1), "l"(Bb + (size_t)r1*256 + k0_ + c81));           \
      asm volatile("cp.async.commit_group;\n");                                  \
    }

  FC_ISSUE(0, 0)
  FC_ISSUE(1, 1)

  for (int c = 0; c < 8; c++){
    int s = c & 1;
    asm volatile("cp.async.wait_group 1;\n" ::: "memory");
    __syncthreads();
    wmma::fragment<wmma::matrix_a,16,16,16,__nv_bfloat16,wmma::row_major> af[2][4];
    wmma::fragment<wmma::matrix_b,16,16,16,__nv_bfloat16,wmma::col_major> bf[2][2];
    #pragma unroll
    for (int kk = 0; kk < 2; kk++){
      #pragma unroll
      for (int i = 0; i < 4; i++) wmma::load_matrix_sync(af[kk][i], &As[s][wm*64+i*16][kk*16], 40);
      #pragma unroll
      for (int jj = 0; jj < 2; jj++) wmma::load_matrix_sync(bf[kk][jj], &Bs[s][wn*32+jj*16][kk*16], 40);
    }
    __syncthreads();
    if (c + 2 < 8) FC_ISSUE(s, c+2)
    #pragma unroll
    for (int kk = 0; kk < 2; kk++)
      #pragma unroll
      for (int i = 0; i < 4; i++)
        #pragma unroll
        for (int jj = 0; jj < 2; jj++)
          wmma::mma_sync(acc[i][jj], af[kk][i], bf[kk][jj], acc[i][jj]);
  }
  #undef FC_ISSUE

  int er = lane >> 1, ec = (lane & 1)*8;
  #pragma unroll
  for (int i = 0; i < 4; i++){
    #pragma unroll
    for (int jj = 0; jj < 2; jj++){
      wmma::store_matrix_sync(&stg[warp][0][0], acc[i][jj], 20, wmma::mem_row_major);
      __syncwarp();
      int mm = bm*128 + wm*64 + i*16 + er;
      int n0 = bn*128 + wn*32 + jj*16 + ec;
      int orow = (mm & 15)*Tsz + (mm >> 4);
      float4 v0 = *(float4*)&stg[warp][er][ec];
      float4 v1 = *(float4*)&stg[warp][er][ec+4];
      v0.x += bias[n0];   v0.y += bias[n0+1]; v0.z += bias[n0+2]; v0.w += bias[n0+3];
      v1.x += bias[n0+4]; v1.y += bias[n0+5]; v1.z += bias[n0+6]; v1.w += bias[n0+7];
      *(float4*)&out[(size_t)orow*Vsz + n0]     = v0;
      *(float4*)&out[(size_t)orow*Vsz + n0 + 4] = v1;
      __syncwarp();
    }
  }
}

// ---------------- in-place log_softmax, row register-resident ----------------
__global__ __launch_bounds__(1024) void lsm_kernel(float* __restrict__ out){
  __shared__ float red[32];
  float4* p4 = (float4*)(out + (size_t)blockIdx.x*Vsz);
  int tid = threadIdx.x;
  float4 v[8];
  float m = -3.4e38f;
  #pragma unroll
  for (int i = 0; i < 8; i++){
    int idx = tid + i*1024;
    if (idx < Vsz/4){
      v[i] = p4[idx];
      m = fmaxf(m, fmaxf(fmaxf(v[i].x, v[i].y), fmaxf(v[i].z, v[i].w)));
    }
  }
  #pragma unroll
  for (int o = 16; o; o >>= 1) m = fmaxf(m, __shfl_xor_sync(0xffffffffu, m, o));
  if ((tid & 31) == 0) red[tid >> 5] = m;
  __syncthreads();
  float mm = red[0];
  #pragma unroll
  for (int ww = 1; ww < 32; ww++) mm = fmaxf(mm, red[ww]);
  __syncthreads();
  float s = 0.f;
  #pragma unroll
  for (int i = 0; i < 8; i++){
    int idx = tid + i*1024;
    if (idx < Vsz/4)
      s += __expf(v[i].x-mm) + __expf(v[i].y-mm) + __expf(v[i].z-mm) + __expf(v[i].w-mm);
  }
  #pragma unroll
  for (int o = 16; o; o >>= 1) s += __shfl_xor_sync(0xffffffffu, s, o);
  if ((tid & 31) == 0) red[tid >> 5] = s;
  __syncthreads();
  float ss = 0.f;
  #pragma unroll
  for (int ww = 0; ww < 32; ww++) ss += red[ww];
  float lse = mm + logf(ss);
  #pragma unroll
  for (int i = 0; i < 8; i++){
    int idx = tid + i*1024;
    if (idx < Vsz/4){
      float4 o4 = v[i];
      o4.x -= lse; o4.y -= lse; o4.z -= lse; o4.w -= lse;
      p4[idx] = o4;
    }
  }
}

extern "C" void kernel_launch(void* const* d_in, const int* in_sizes, int n_in,
                              void* d_out, int out_size) {
  const int*   x    = (const int*)  d_in[0];
  const float* emb  = (const float*)d_in[1];
  const float* Wi0  = (const float*)d_in[2];
  const float* Wh0  = (const float*)d_in[3];
  const float* b0   = (const float*)d_in[4];
  const float* Wi1  = (const float*)d_in[5];
  const float* Wh1  = (const float*)d_in[6];
  const float* b1   = (const float*)d_in[7];
  const float* Wi2  = (const float*)d_in[8];
  const float* Wh2  = (const float*)d_in[9];
  const float* b2   = (const float*)d_in[10];
  const float* fcW  = (const float*)d_in[11];
  const float* fcb  = (const float*)d_in[12];
  float* out = (float*)d_out;

  // launch order arranged so ncu (-s 5 -c 1) captures scan_kernel (index 5)
  embed_kernel<<<Msz, 256>>>(x, emb);          // 0
  padwi0_kernel<<<G4, 256>>>(Wi0);             // 1

  dim3 xg(16, 64);
  xproj_kernel<<<xg, 256>>>(0, Wi0, b0);       // 2
  scan_kernel<<<128, 512>>>(Wh0, 0);           // 3
  xproj_kernel<<<xg, 256>>>(1, Wi1, b1);       // 4
  scan_kernel<<<128, 512>>>(Wh1, 0);           // 5  <-- profiled
  xproj_kernel<<<xg, 256>>>(1, Wi2, b2);       // 6
  scan_kernel<<<128, 512>>>(Wh2, 1);           // 7  writes g_hb directly

  convwb_kernel<<<Vsz, 256>>>(fcW);            // 8
  dim3 fg(Vsz/128, Msz/128);
  fc_kernel<<<fg, 256>>>(fcb, out);            // 9
  lsm_kernel<<<Msz, 1024>>>(out);              // 10
}

// round 9
// speedup vs baseline: 2.3644x; 1.2192x over previous
#include <cuda_runtime.h>
#include <cuda_bf16.h>
#include <mma.h>
#include <cstdint>
using namespace nvcuda;
typedef unsigned long long ull;
typedef unsigned int u32;

#define Bsz 16
#define Tsz 256
#define Esz 200
#define Hsz 256
#define Vsz 32000
#define G4  1024
#define Msz 4096   // B*T rows, time-major: r = t*16 + b

__device__ float g_x[Msz*Hsz];
__device__ float g_xg[Msz*G4];
__device__ float g_hall[Msz*Hsz];
__device__ float g_wi0p[G4*Hsz];
__device__ __nv_bfloat16 g_hb[Msz*Hsz];
__device__ __nv_bfloat16 g_wb[(size_t)Vsz*Hsz];

__device__ __forceinline__ float sigmoidf_(float x){ return 1.f/(1.f+__expf(-x)); }
__device__ __forceinline__ float tanhf_(float x){ return 1.f - 2.f/(__expf(2.f*x)+1.f); }

__device__ __forceinline__ ull pk2(float a, float b){
  ull r; asm("mov.b64 %0,{%1,%2};" : "=l"(r) : "f"(a), "f"(b)); return r;
}
__device__ __forceinline__ void upk2(ull v, float& a, float& b){
  asm("mov.b64 {%0,%1},%2;" : "=f"(a), "=f"(b) : "l"(v));
}
__device__ __forceinline__ ull ffma2(ull a, ull b, ull c){
  ull d; asm("fma.rn.f32x2 %0,%1,%2,%3;" : "=l"(d) : "l"(a), "l"(b), "l"(c)); return d;
}

// ---------------- prep ----------------
__global__ void embed_kernel(const int* __restrict__ x, const float* __restrict__ emb){
  int idx = blockIdx.x*256 + threadIdx.x;
  int r = idx >> 8, k = idx & 255;
  int t = r >> 4, b = r & 15;
  float v = 0.f;
  if (k < Esz) v = emb[(size_t)x[b*Tsz + t]*Esz + k];
  g_x[idx] = v;
}

__global__ void padwi0_kernel(const float* __restrict__ Wi0){
  int idx = blockIdx.x*256 + threadIdx.x;
  int j = idx >> 8, k = idx & 255;
  g_wi0p[idx] = (k < Esz) ? Wi0[j*Esz + k] : 0.f;
}

__global__ void convwb_kernel(const float* __restrict__ fcW){
  size_t idx = (size_t)blockIdx.x*256 + threadIdx.x;
  g_wb[idx] = __float2bfloat16(fcW[idx]);
}

// ---------------- input-proj GEMM: g_xg[r][n] = X[r]·W[n] + bias[n] ----------------
__global__ __launch_bounds__(256) void xproj_kernel(int sel,
                                                    const float* __restrict__ Wext,
                                                    const float* __restrict__ bias){
  const float* __restrict__ X = sel ? g_hall : g_x;
  const float* __restrict__ W = sel ? Wext  : g_wi0p;
  __shared__ float As[16][64];
  __shared__ float Bs[16][64];
  int tid = threadIdx.x;
  int tx = tid & 15, ty = tid >> 4;
  int m0 = blockIdx.y*64, n0 = blockIdx.x*64;
  int lr = tid >> 2, lc = (tid & 3)*4;
  float acc[4][4] = {};
  for (int k0 = 0; k0 < 256; k0 += 16){
    float4 xv = *(const float4*)&X[(m0+lr)*256 + k0 + lc];
    float4 wv = *(const float4*)&W[(n0+lr)*256 + k0 + lc];
    __syncthreads();
    As[lc][lr]=xv.x; As[lc+1][lr]=xv.y; As[lc+2][lr]=xv.z; As[lc+3][lr]=xv.w;
    Bs[lc][lr]=wv.x; Bs[lc+1][lr]=wv.y; Bs[lc+2][lr]=wv.z; Bs[lc+3][lr]=wv.w;
    __syncthreads();
    #pragma unroll
    for (int k = 0; k < 16; k++){
      float4 a = *(float4*)&As[k][ty*4];
      float4 b = *(float4*)&Bs[k][tx*4];
      acc[0][0]+=a.x*b.x; acc[0][1]+=a.x*b.y; acc[0][2]+=a.x*b.z; acc[0][3]+=a.x*b.w;
      acc[1][0]+=a.y*b.x; acc[1][1]+=a.y*b.y; acc[1][2]+=a.y*b.z; acc[1][3]+=a.y*b.w;
      acc[2][0]+=a.z*b.x; acc[2][1]+=a.z*b.y; acc[2][2]+=a.z*b.z; acc[2][3]+=a.z*b.w;
      acc[3][0]+=a.w*b.x; acc[3][1]+=a.w*b.y; acc[3][2]+=a.w*b.z; acc[3][3]+=a.w*b.w;
    }
  }
  #pragma unroll
  for (int i = 0; i < 4; i++){
    int mrow = m0 + ty*4 + i;
    #pragma unroll
    for (int j = 0; j < 4; j++){
      int n = n0 + tx*4 + j;
      g_xg[mrow*G4 + n] = acc[i][j] + bias[n];
    }
  }
}

// ---------------- LSTM scan: 8-CTA cluster / batch, st.async h handoff ----------------
// last==1: write bf16 h into g_hb (final layer) instead of f32 g_hall.
__global__ void __launch_bounds__(512,1) __cluster_dims__(8,1,1)
scan_kernel(const float* __restrict__ Wh, int last){
  __shared__ __align__(16) float hs[2][256];   // ping-pong replicated h
  __shared__ __align__(8)  ull mbar[2];        // tx barriers: full[p]
  int tid = threadIdx.x;
  int w = tid >> 5, l = tid & 31;
  int g4 = l >> 3, kl = l & 7;
  u32 rank; asm("mov.u32 %0, %%cluster_ctarank;" : "=r"(rank));
  int b = blockIdx.x >> 3;
  int j = (int)rank;

  // register-resident weights: 2 gate-rows x 8 chunks x 2 f32x2
  ull wgt[2][8][2];
  #pragma unroll
  for (int r = 0; r < 2; r++){
    int rg = 2*g4 + r;             // 0..7
    int u = rg >> 2, gate = rg & 3;
    int n = 32*j + 2*w + u;
    const float4* Wr = (const float4*)(Wh + (gate*256 + n)*256);
    #pragma unroll
    for (int m = 0; m < 8; m++){
      float4 v = Wr[kl + 8*m];
      wgt[r][m][0] = pk2(v.x, v.y);
      wgt[r][m][1] = pk2(v.z, v.w);
    }
  }
  if (tid < 256) hs[0][tid] = 0.f;

  u32 hbase, mbase;
  asm("{.reg .u64 t; cvta.to.shared.u64 t,%1; cvt.u32.u64 %0,t;}" : "=r"(hbase) : "l"(&hs[0][0]));
  asm("{.reg .u64 t; cvta.to.shared.u64 t,%1; cvt.u32.u64 %0,t;}" : "=r"(mbase) : "l"(&mbar[0]));

  if (tid == 0){
    asm volatile("mbarrier.init.shared.b64 [%0],%1;" :: "r"(mbase),    "r"(1) : "memory");
    asm volatile("mbarrier.init.shared.b64 [%0],%1;" :: "r"(mbase+8u), "r"(1) : "memory");
    // arm both barriers: 256 act-lane stores x 4B = 1024 bytes per phase
    asm volatile("mbarrier.arrive.expect_tx.shared.b64 _,[%0],%1;" :: "r"(mbase),    "r"(1024) : "memory");
    asm volatile("mbarrier.arrive.expect_tx.shared.b64 _,[%0],%1;" :: "r"(mbase+8u), "r"(1024) : "memory");
  }
  __syncthreads();

  bool act = ((l & 15) == 0);      // lanes 0 and 16
  int u_loc = l >> 4;
  int n_act = 32*j + 2*w + u_loc;
  float creg = 0.f;
  float xgc[4] = {0.f,0.f,0.f,0.f};
  float xgn[4] = {0.f,0.f,0.f,0.f};
  if (act){
    #pragma unroll
    for (int g = 0; g < 4; g++){
      xgc[g] = __ldg(&g_xg[(0*16+b)*G4 + g*256 + n_act]);
      xgn[g] = __ldg(&g_xg[(1*16+b)*G4 + g*256 + n_act]);
    }
  }

  // one cluster sync: mbarrier init/arm + hs[0] zeros visible before any remote st.async
  asm volatile("barrier.cluster.arrive.aligned;" ::: "memory");
  asm volatile("barrier.cluster.wait.aligned;" ::: "memory");

  for (int t = 0; t < 256; t++){
    if (t){
      u32 ma = mbase + (u32)(t & 1)*8u;
      u32 par = ((u32)(t - 1) >> 1) & 1u;
      u32 done;
      asm volatile(
        "{\n\t.reg .pred p;\n"
        "\tmbarrier.try_wait.parity.acquire.cta.shared::cta.b64 p,[%1],%2;\n"
        "\tselp.b32 %0,1,0,p;\n\t}"
        : "=r"(done) : "r"(ma), "r"(par) : "memory");
      if (!done){
        asm volatile(
          "{\n\t.reg .pred P1;\n"
          "WL%=:\n\tmbarrier.try_wait.parity.acquire.cta.shared::cta.b64 P1,[%0],%1,0x989680;\n"
          "\t@P1 bra WD%=;\n"
          "\tbra.uni WL%=;\n"
          "WD%=:\n\t}"
          :: "r"(ma), "r"(par) : "memory");
      }
      // re-arm this barrier for its next phase (consumed at t+2)
      if (tid == 0)
        asm volatile("mbarrier.arrive.expect_tx.shared.b64 _,[%0],%1;" :: "r"(ma), "r"(1024) : "memory");
    }
    u32 rb = hbase + (u32)(t & 1)*1024u;
    ull a0 = 0ull, a1 = 0ull;
    #pragma unroll
    for (int m = 0; m < 8; m++){
      ull h0, h1;
      asm("ld.shared.v2.u64 {%0,%1},[%2];" : "=l"(h0), "=l"(h1)
          : "r"(rb + (u32)(kl + 8*m)*16u));
      a0 = ffma2(wgt[0][m][0], h0, a0);
      a0 = ffma2(wgt[0][m][1], h1, a0);
      a1 = ffma2(wgt[1][m][0], h0, a1);
      a1 = ffma2(wgt[1][m][1], h1, a1);
    }
    float s0, s1, lo, hi;
    upk2(a0, lo, hi); s0 = lo + hi;
    upk2(a1, lo, hi); s1 = lo + hi;
    #pragma unroll
    for (int off = 1; off < 8; off <<= 1){
      s0 += __shfl_xor_sync(0xffffffffu, s0, off);
      s1 += __shfl_xor_sync(0xffffffffu, s1, off);
    }
    float gg = __shfl_xor_sync(0xffffffffu, s0, 8);  // partner group's gate g
    float go = __shfl_xor_sync(0xffffffffu, s1, 8);  // partner group's gate o
    if (act){
      float gi = s0 + xgc[0];
      float gf = s1 + xgc[1];
      float gG = gg + xgc[2];
      float gO = go + xgc[3];
      float iv = sigmoidf_(gi), fv = sigmoidf_(gf);
      float cv = tanhf_(gG),   ov = sigmoidf_(gO);
      creg = fv*creg + iv*cv;
      float hv = ov*tanhf_(creg);
      if (t < 255){
        u32 ha = hbase + (u32)((t+1) & 1)*1024u + (u32)n_act*4u;
        u32 me = mbase + (u32)((t+1) & 1)*8u;
        u32 hvb = __float_as_uint(hv);
        #pragma unroll
        for (int p = 0; p < 8; p++){
          u32 ra, rm;
          asm("mapa.shared::cluster.u32 %0,%1,%2;" : "=r"(ra) : "r"(ha), "r"(p));
          asm("mapa.shared::cluster.u32 %0,%1,%2;" : "=r"(rm) : "r"(me), "r"(p));
          asm volatile("st.async.shared::cluster.mbarrier::complete_tx::bytes.b32 [%0],%1,[%2];"
                       :: "r"(ra), "r"(hvb), "r"(rm) : "memory");
        }
      }
      if (last) g_hb[(t*16+b)*256 + n_act] = __float2bfloat16(hv);
      else      g_hall[(t*16+b)*256 + n_act] = hv;
      xgc[0]=xgn[0]; xgc[1]=xgn[1]; xgc[2]=xgn[2]; xgc[3]=xgn[3];
      if (t + 2 < 256){
        #pragma unroll
        for (int g = 0; g < 4; g++)
          xgn[g] = __ldg(&g_xg[((t+2)*16+b)*G4 + g*256 + n_act]);
      }
    }
  }
  // all CTAs must stay alive until peers stop storing into this CTA's smem
  asm volatile("barrier.cluster.arrive.aligned;" ::: "memory");
  asm volatile("barrier.cluster.wait.aligned;" ::: "memory");
}

// ---------------- FC GEMM bf16 WMMA, cp.async double-buffered ----------------
__global__ __launch_bounds__(256) void fc_kernel(const float* __restrict__ bias,
                                                 float* __restrict__ out){
  __shared__ __nv_bfloat16 As[2][128][40];
  __shared__ __nv_bfloat16 Bs[2][128][40];
  __shared__ float stg[8][16][20];
  int bn = blockIdx.x, bm = blockIdx.y;
  int tid = threadIdx.x;
  int warp = tid >> 5, lane = tid & 31;
  int wm = warp >> 2, wn = warp & 3;     // 2 x 4 warps; warp tile 64(M) x 32(N)
  const __nv_bfloat16* Ab = g_hb + (size_t)(bm*128)*256;
  const __nv_bfloat16* Bb = g_wb + (size_t)(bn*128)*256;

  int cid0 = tid*2;
  int r0 = cid0 >> 2,      c80 = (cid0 & 3)*8;
  int r1 = (cid0+1) >> 2,  c81 = ((cid0+1) & 3)*8;

  wmma::fragment<wmma::accumulator,16,16,16,float> acc[4][2];
  #pragma unroll
  for (int i = 0; i < 4; i++)
    #pragma unroll
    for (int jj = 0; jj < 2; jj++) wmma::fill_fragment(acc[i][jj], 0.f);

  #define FC_ISSUE(stage, c)                                                     \
    {                                                                            \
      int k0_ = (c)*32;                                                          \
      u32 sa0 = (u32)__cvta_generic_to_shared(&As[stage][r0][c80]);              \
      u32 sb0 = (u32)__cvta_generic_to_shared(&Bs[stage][r0][c80]);              \
      u32 sa1 = (u32)__cvta_generic_to_shared(&As[stage][r1][c81]);              \
      u32 sb1 = (u32)__cvta_generic_to_shared(&Bs[stage][r1][c81]);              \
      asm volatile("cp.async.cg.shared.global [%0],[%1],16;\n"                   \
                   :: "r"(sa0), "l"(Ab + (size_t)r0*256 + k0_ + c80));           \
      asm volatile("cp.async.cg.shared.global [%0],[%1],16;\n"                   \
                   :: "r"(sb0), "l"(Bb + (size_t)r0*256 + k0_ + c80));           \
      asm volatile("cp.async.cg.shared.global [%0],[%1],16;\n"                   \
                   :: "r"(sa1), "l"(Ab + (size_t)r1*256 + k0_ + c81));           \
      asm volatile("cp.async.cg.shared.global [%0],[%1],16;\n"                   \
                   :: "r"(sb1), "l"(Bb + (size_t)r1*256 + k0_ + c81));           \
      asm volatile("cp.async.commit_group;\n");                                  \
    }

  FC_ISSUE(0, 0)
  FC_ISSUE(1, 1)

  for (int c = 0; c < 8; c++){
    int s = c & 1;
    asm volatile("cp.async.wait_group 1;\n" ::: "memory");
    __syncthreads();
    wmma::fragment<wmma::matrix_a,16,16,16,__nv_bfloat16,wmma::row_major> af[2][4];
    wmma::fragment<wmma::matrix_b,16,16,16,__nv_bfloat16,wmma::col_major> bf[2][2];
    #pragma unroll
    for (int kk = 0; kk < 2; kk++){
      #pragma unroll
      for (int i = 0; i < 4; i++) wmma::load_matrix_sync(af[kk][i], &As[s][wm*64+i*16][kk*16], 40);
      #pragma unroll
      for (int jj = 0; jj < 2; jj++) wmma::load_matrix_sync(bf[kk][jj], &Bs[s][wn*32+jj*16][kk*16], 40);
    }
    __syncthreads();
    if (c + 2 < 8) FC_ISSUE(s, c+2)
    #pragma unroll
    for (int kk = 0; kk < 2; kk++)
      #pragma unroll
      for (int i = 0; i < 4; i++)
        #pragma unroll
        for (int jj = 0; jj < 2; jj++)
          wmma::mma_sync(acc[i][jj], af[kk][i], bf[kk][jj], acc[i][jj]);
  }
  #undef FC_ISSUE

  int er = lane >> 1, ec = (lane & 1)*8;
  #pragma unroll
  for (int i = 0; i < 4; i++){
    #pragma unroll
    for (int jj = 0; jj < 2; jj++){
      wmma::store_matrix_sync(&stg[warp][0][0], acc[i][jj], 20, wmma::mem_row_major);
      __syncwarp();
      int mm = bm*128 + wm*64 + i*16 + er;
      int n0 = bn*128 + wn*32 + jj*16 + ec;
      int orow = (mm & 15)*Tsz + (mm >> 4);
      float4 v0 = *(float4*)&stg[warp][er][ec];
      float4 v1 = *(float4*)&stg[warp][er][ec+4];
      v0.x += bias[n0];   v0.y += bias[n0+1]; v0.z += bias[n0+2]; v0.w += bias[n0+3];
      v1.x += bias[n0+4]; v1.y += bias[n0+5]; v1.z += bias[n0+6]; v1.w += bias[n0+7];
      *(float4*)&out[(size_t)orow*Vsz + n0]     = v0;
      *(float4*)&out[(size_t)orow*Vsz + n0 + 4] = v1;
      __syncwarp();
    }
  }
}

// ---------------- in-place log_softmax, row register-resident ----------------
__global__ __launch_bounds__(1024) void lsm_kernel(float* __restrict__ out){
  __shared__ float red[32];
  float4* p4 = (float4*)(out + (size_t)blockIdx.x*Vsz);
  int tid = threadIdx.x;
  float4 v[8];
  float m = -3.4e38f;
  #pragma unroll
  for (int i = 0; i < 8; i++){
    int idx = tid + i*1024;
    if (idx < Vsz/4){
      v[i] = p4[idx];
      m = fmaxf(m, fmaxf(fmaxf(v[i].x, v[i].y), fmaxf(v[i].z, v[i].w)));
    }
  }
  #pragma unroll
  for (int o = 16; o; o >>= 1) m = fmaxf(m, __shfl_xor_sync(0xffffffffu, m, o));
  if ((tid & 31) == 0) red[tid >> 5] = m;
  __syncthreads();
  float mm = red[0];
  #pragma unroll
  for (int ww = 1; ww < 32; ww++) mm = fmaxf(mm, red[ww]);
  __syncthreads();
  float s = 0.f;
  #pragma unroll
  for (int i = 0; i < 8; i++){
    int idx = tid + i*1024;
    if (idx < Vsz/4)
      s += __expf(v[i].x-mm) + __expf(v[i].y-mm) + __expf(v[i].z-mm) + __expf(v[i].w-mm);
  }
  #pragma unroll
  for (int o = 16; o; o >>= 1) s += __shfl_xor_sync(0xffffffffu, s, o);
  if ((tid & 31) == 0) red[tid >> 5] = s;
  __syncthreads();
  float ss = 0.f;
  #pragma unroll
  for (int ww = 0; ww < 32; ww++) ss += red[ww];
  float lse = mm + logf(ss);
  #pragma unroll
  for (int i = 0; i < 8; i++){
    int idx = tid + i*1024;
    if (idx < Vsz/4){
      float4 o4 = v[i];
      o4.x -= lse; o4.y -= lse; o4.z -= lse; o4.w -= lse;
      p4[idx] = o4;
    }
  }
}

extern "C" void kernel_launch(void* const* d_in, const int* in_sizes, int n_in,
                              void* d_out, int out_size) {
  const int*   x    = (const int*)  d_in[0];
  const float* emb  = (const float*)d_in[1];
  const float* Wi0  = (const float*)d_in[2];
  const float* Wh0  = (const float*)d_in[3];
  const float* b0   = (const float*)d_in[4];
  const float* Wi1  = (const float*)d_in[5];
  const float* Wh1  = (const float*)d_in[6];
  const float* b1   = (const float*)d_in[7];
  const float* Wi2  = (const float*)d_in[8];
  const float* Wh2  = (const float*)d_in[9];
  const float* b2   = (const float*)d_in[10];
  const float* fcW  = (const float*)d_in[11];
  const float* fcb  = (const float*)d_in[12];
  float* out = (float*)d_out;

  // launch order arranged so ncu (-s 5 -c 1) captures scan_kernel (index 5)
  embed_kernel<<<Msz, 256>>>(x, emb);          // 0
  padwi0_kernel<<<G4, 256>>>(Wi0);             // 1

  dim3 xg(16, 64);
  xproj_kernel<<<xg, 256>>>(0, Wi0, b0);       // 2
  scan_kernel<<<128, 512>>>(Wh0, 0);           // 3
  xproj_kernel<<<xg, 256>>>(1, Wi1, b1);       // 4
  scan_kernel<<<128, 512>>>(Wh1, 0);           // 5  <-- profiled
  xproj_kernel<<<xg, 256>>>(1, Wi2, b2);       // 6
  scan_kernel<<<128, 512>>>(Wh2, 1);           // 7  writes g_hb directly

  convwb_kernel<<<Vsz, 256>>>(fcW);            // 8
  dim3 fg(Vsz/128, Msz/128);
  fc_kernel<<<fg, 256>>>(fcb, out);            // 9
  lsm_kernel<<<Msz, 1024>>>(out);              // 10
}

// round 10
// speedup vs baseline: 2.4907x; 1.0534x over previous
#include <cuda_runtime.h>
#include <cuda_bf16.h>
#include <mma.h>
#include <cstdint>
using namespace nvcuda;
typedef unsigned long long ull;
typedef unsigned int u32;

#define Bsz 16
#define Tsz 256
#define Esz 200
#define Hsz 256
#define Vsz 32000
#define G4  1024
#define Msz 4096   // B*T rows, time-major: r = t*16 + b

__device__ float g_x[Msz*Hsz];
__device__ float g_xg[Msz*G4];
__device__ float g_hall[Msz*Hsz];
__device__ float g_wi0p[G4*Hsz];
__device__ __nv_bfloat16 g_hb[Msz*Hsz];
__device__ __nv_bfloat16 g_wb[(size_t)Vsz*Hsz];

__device__ __forceinline__ float sigmoidf_(float x){ return 1.f/(1.f+__expf(-x)); }
__device__ __forceinline__ float tanhf_(float x){ return 1.f - 2.f/(__expf(2.f*x)+1.f); }

__device__ __forceinline__ ull pk2(float a, float b){
  ull r; asm("mov.b64 %0,{%1,%2};" : "=l"(r) : "f"(a), "f"(b)); return r;
}
__device__ __forceinline__ void upk2(ull v, float& a, float& b){
  asm("mov.b64 {%0,%1},%2;" : "=f"(a), "=f"(b) : "l"(v));
}
__device__ __forceinline__ ull ffma2(ull a, ull b, ull c){
  ull d; asm("fma.rn.f32x2 %0,%1,%2,%3;" : "=l"(d) : "l"(a), "l"(b), "l"(c)); return d;
}

// ---------------- prep ----------------
__global__ void embed_kernel(const int* __restrict__ x, const float* __restrict__ emb){
  int idx = blockIdx.x*256 + threadIdx.x;
  int r = idx >> 8, k = idx & 255;
  int t = r >> 4, b = r & 15;
  float v = 0.f;
  if (k < Esz) v = emb[(size_t)x[b*Tsz + t]*Esz + k];
  g_x[idx] = v;
}

__global__ void padwi0_kernel(const float* __restrict__ Wi0){
  int idx = blockIdx.x*256 + threadIdx.x;
  int j = idx >> 8, k = idx & 255;
  g_wi0p[idx] = (k < Esz) ? Wi0[j*Esz + k] : 0.f;
}

__global__ void convwb_kernel(const float* __restrict__ fcW){
  size_t idx = (size_t)blockIdx.x*256 + threadIdx.x;
  g_wb[idx] = __float2bfloat16(fcW[idx]);
}

// ---------------- input-proj GEMM: g_xg[r][n] = X[r]·W[n] + bias[n] ----------------
__global__ __launch_bounds__(256) void xproj_kernel(int sel,
                                                    const float* __restrict__ Wext,
                                                    const float* __restrict__ bias){
  const float* __restrict__ X = sel ? g_hall : g_x;
  const float* __restrict__ W = sel ? Wext  : g_wi0p;
  __shared__ float As[16][64];
  __shared__ float Bs[16][64];
  int tid = threadIdx.x;
  int tx = tid & 15, ty = tid >> 4;
  int m0 = blockIdx.y*64, n0 = blockIdx.x*64;
  int lr = tid >> 2, lc = (tid & 3)*4;
  float acc[4][4] = {};
  for (int k0 = 0; k0 < 256; k0 += 16){
    float4 xv = *(const float4*)&X[(m0+lr)*256 + k0 + lc];
    float4 wv = *(const float4*)&W[(n0+lr)*256 + k0 + lc];
    __syncthreads();
    As[lc][lr]=xv.x; As[lc+1][lr]=xv.y; As[lc+2][lr]=xv.z; As[lc+3][lr]=xv.w;
    Bs[lc][lr]=wv.x; Bs[lc+1][lr]=wv.y; Bs[lc+2][lr]=wv.z; Bs[lc+3][lr]=wv.w;
    __syncthreads();
    #pragma unroll
    for (int k = 0; k < 16; k++){
      float4 a = *(float4*)&As[k][ty*4];
      float4 b = *(float4*)&Bs[k][tx*4];
      acc[0][0]+=a.x*b.x; acc[0][1]+=a.x*b.y; acc[0][2]+=a.x*b.z; acc[0][3]+=a.x*b.w;
      acc[1][0]+=a.y*b.x; acc[1][1]+=a.y*b.y; acc[1][2]+=a.y*b.z; acc[1][3]+=a.y*b.w;
      acc[2][0]+=a.z*b.x; acc[2][1]+=a.z*b.y; acc[2][2]+=a.z*b.z; acc[2][3]+=a.z*b.w;
      acc[3][0]+=a.w*b.x; acc[3][1]+=a.w*b.y; acc[3][2]+=a.w*b.z; acc[3][3]+=a.w*b.w;
    }
  }
  #pragma unroll
  for (int i = 0; i < 4; i++){
    int mrow = m0 + ty*4 + i;
    #pragma unroll
    for (int j = 0; j < 4; j++){
      int n = n0 + tx*4 + j;
      g_xg[mrow*G4 + n] = acc[i][j] + bias[n];
    }
  }
}

// ---------------- LSTM scan: 8-CTA cluster handles TWO batches, interleaved ----------------
// grid = 64 CTAs = 8 clusters; cluster c owns batches 2c, 2c+1.
// last==1: write bf16 h into g_hb (final layer) instead of f32 g_hall.
__global__ void __launch_bounds__(512,1) __cluster_dims__(8,1,1)
scan_kernel(const float* __restrict__ Wh, int last){
  __shared__ __align__(16) float hs[2][2][256];  // [batch][pingpong][h]
  __shared__ __align__(8)  ull mbar[2][2];       // [batch][pingpong]
  int tid = threadIdx.x;
  int w = tid >> 5, l = tid & 31;
  int g4 = l >> 3, kl = l & 7;
  u32 rank; asm("mov.u32 %0, %%cluster_ctarank;" : "=r"(rank));
  int c = blockIdx.x >> 3;
  int j = (int)rank;

  // register-resident weights: 2 gate-rows x 8 chunks x 2 f32x2 (shared by both batches)
  ull wgt[2][8][2];
  #pragma unroll
  for (int r = 0; r < 2; r++){
    int rg = 2*g4 + r;             // 0..7
    int u = rg >> 2, gate = rg & 3;
    int n = 32*j + 2*w + u;
    const float4* Wr = (const float4*)(Wh + (gate*256 + n)*256);
    #pragma unroll
    for (int m = 0; m < 8; m++){
      float4 v = Wr[kl + 8*m];
      wgt[r][m][0] = pk2(v.x, v.y);
      wgt[r][m][1] = pk2(v.z, v.w);
    }
  }
  if (tid < 256){ hs[0][0][tid] = 0.f; hs[1][0][tid] = 0.f; }

  u32 hbase, mbase;
  asm("{.reg .u64 t; cvta.to.shared.u64 t,%1; cvt.u32.u64 %0,t;}" : "=r"(hbase) : "l"(&hs[0][0][0]));
  asm("{.reg .u64 t; cvta.to.shared.u64 t,%1; cvt.u32.u64 %0,t;}" : "=r"(mbase) : "l"(&mbar[0][0]));

  if (tid == 0){
    #pragma unroll
    for (int q = 0; q < 4; q++){
      asm volatile("mbarrier.init.shared.b64 [%0],%1;" :: "r"(mbase + q*8u), "r"(1) : "memory");
      asm volatile("mbarrier.arrive.expect_tx.shared.b64 _,[%0],%1;" :: "r"(mbase + q*8u), "r"(1024) : "memory");
    }
  }
  __syncthreads();

  bool act = ((l & 15) == 0);      // lanes 0 and 16
  int u_loc = l >> 4;
  int n_act = 32*j + 2*w + u_loc;
  float creg[2] = {0.f, 0.f};
  float xgc[2][4] = {};
  float xgn[2][4] = {};
  if (act){
    #pragma unroll
    for (int bb = 0; bb < 2; bb++){
      int b = 2*c + bb;
      #pragma unroll
      for (int g = 0; g < 4; g++){
        xgc[bb][g] = __ldg(&g_xg[(0*16+b)*G4 + g*256 + n_act]);
        xgn[bb][g] = __ldg(&g_xg[(1*16+b)*G4 + g*256 + n_act]);
      }
    }
  }

  // one cluster sync: mbarrier init/arm + hs zeros visible before any remote st.async
  asm volatile("barrier.cluster.arrive.aligned;" ::: "memory");
  asm volatile("barrier.cluster.wait.aligned;" ::: "memory");

  for (int t = 0; t < 256; t++){
    #pragma unroll
    for (int bb = 0; bb < 2; bb++){
      int b = 2*c + bb;
      if (t){
        u32 ma = mbase + (u32)bb*16u + (u32)(t & 1)*8u;
        u32 par = ((u32)(t - 1) >> 1) & 1u;
        u32 done;
        asm volatile(
          "{\n\t.reg .pred p;\n"
          "\tmbarrier.try_wait.parity.acquire.cta.shared::cta.b64 p,[%1],%2;\n"
          "\tselp.b32 %0,1,0,p;\n\t}"
          : "=r"(done) : "r"(ma), "r"(par) : "memory");
        if (!done){
          asm volatile(
            "{\n\t.reg .pred P1;\n"
            "WL%=:\n\tmbarrier.try_wait.parity.acquire.cta.shared::cta.b64 P1,[%0],%1,0x989680;\n"
            "\t@P1 bra WD%=;\n"
            "\tbra.uni WL%=;\n"
            "WD%=:\n\t}"
            :: "r"(ma), "r"(par) : "memory");
        }
        if (tid == 0)
          asm volatile("mbarrier.arrive.expect_tx.shared.b64 _,[%0],%1;" :: "r"(ma), "r"(1024) : "memory");
      }
      u32 rb = hbase + (u32)bb*2048u + (u32)(t & 1)*1024u;
      ull a0 = 0ull, a1 = 0ull;
      #pragma unroll
      for (int m = 0; m < 8; m++){
        ull h0, h1;
        asm("ld.shared.v2.u64 {%0,%1},[%2];" : "=l"(h0), "=l"(h1)
            : "r"(rb + (u32)(kl + 8*m)*16u));
        a0 = ffma2(wgt[0][m][0], h0, a0);
        a0 = ffma2(wgt[0][m][1], h1, a0);
        a1 = ffma2(wgt[1][m][0], h0, a1);
        a1 = ffma2(wgt[1][m][1], h1, a1);
      }
      float s0, s1, lo, hi;
      upk2(a0, lo, hi); s0 = lo + hi;
      upk2(a1, lo, hi); s1 = lo + hi;
      #pragma unroll
      for (int off = 1; off < 8; off <<= 1){
        s0 += __shfl_xor_sync(0xffffffffu, s0, off);
        s1 += __shfl_xor_sync(0xffffffffu, s1, off);
      }
      float gg = __shfl_xor_sync(0xffffffffu, s0, 8);  // partner group's gate g
      float go = __shfl_xor_sync(0xffffffffu, s1, 8);  // partner group's gate o
      if (act){
        float gi = s0 + xgc[bb][0];
        float gf = s1 + xgc[bb][1];
        float gG = gg + xgc[bb][2];
        float gO = go + xgc[bb][3];
        float iv = sigmoidf_(gi), fv = sigmoidf_(gf);
        float cv = tanhf_(gG),   ov = sigmoidf_(gO);
        creg[bb] = fv*creg[bb] + iv*cv;
        float hv = ov*tanhf_(creg[bb]);
        if (t < 255){
          u32 ha = hbase + (u32)bb*2048u + (u32)((t+1) & 1)*1024u + (u32)n_act*4u;
          u32 me = mbase + (u32)bb*16u + (u32)((t+1) & 1)*8u;
          u32 hvb = __float_as_uint(hv);
          #pragma unroll
          for (int p = 0; p < 8; p++){
            u32 ra, rm;
            asm("mapa.shared::cluster.u32 %0,%1,%2;" : "=r"(ra) : "r"(ha), "r"(p));
            asm("mapa.shared::cluster.u32 %0,%1,%2;" : "=r"(rm) : "r"(me), "r"(p));
            asm volatile("st.async.shared::cluster.mbarrier::complete_tx::bytes.b32 [%0],%1,[%2];"
                         :: "r"(ra), "r"(hvb), "r"(rm) : "memory");
          }
        }
        if (last) g_hb[(t*16+b)*256 + n_act] = __float2bfloat16(hv);
        else      g_hall[(t*16+b)*256 + n_act] = hv;
        xgc[bb][0]=xgn[bb][0]; xgc[bb][1]=xgn[bb][1]; xgc[bb][2]=xgn[bb][2]; xgc[bb][3]=xgn[bb][3];
        if (t + 2 < 256){
          #pragma unroll
          for (int g = 0; g < 4; g++)
            xgn[bb][g] = __ldg(&g_xg[((t+2)*16+b)*G4 + g*256 + n_act]);
        }
      }
    }
  }
  // all CTAs stay alive until peers stop storing into this CTA's smem
  asm volatile("barrier.cluster.arrive.aligned;" ::: "memory");
  asm volatile("barrier.cluster.wait.aligned;" ::: "memory");
}

// ---------------- FC GEMM bf16 WMMA, cp.async double-buffered ----------------
__global__ __launch_bounds__(256) void fc_kernel(const float* __restrict__ bias,
                                                 float* __restrict__ out){
  __shared__ __nv_bfloat16 As[2][128][40];
  __shared__ __nv_bfloat16 Bs[2][128][40];
  __shared__ float stg[8][16][20];
  int bn = blockIdx.x, bm = blockIdx.y;
  int tid = threadIdx.x;
  int warp = tid >> 5, lane = tid & 31;
  int wm = warp >> 2, wn = warp & 3;     // 2 x 4 warps; warp tile 64(M) x 32(N)
  const __nv_bfloat16* Ab = g_hb + (size_t)(bm*128)*256;
  const __nv_bfloat16* Bb = g_wb + (size_t)(bn*128)*256;

  int cid0 = tid*2;
  int r0 = cid0 >> 2,      c80 = (cid0 & 3)*8;
  int r1 = (cid0+1) >> 2,  c81 = ((cid0+1) & 3)*8;

  wmma::fragment<wmma::accumulator,16,16,16,float> acc[4][2];
  #pragma unroll
  for (int i = 0; i < 4; i++)
    #pragma unroll
    for (int jj = 0; jj < 2; jj++) wmma::fill_fragment(acc[i][jj], 0.f);

  #define FC_ISSUE(stage, c)                                                     \
    {                                                                            \
      int k0_ = (c)*32;                                                          \
      u32 sa0 = (u32)__cvta_generic_to_shared(&As[stage][r0][c80]);              \
      u32 sb0 = (u32)__cvta_generic_to_shared(&Bs[stage][r0][c80]);              \
      u32 sa1 = (u32)__cvta_generic_to_shared(&As[stage][r1][c81]);              \
      u32 sb1 = (u32)__cvta_generic_to_shared(&Bs[stage][r1][c81]);              \
      asm volatile("cp.async.cg.shared.global [%0],[%1],16;\n"                   \
                   :: "r"(sa0), "l"(Ab + (size_t)r0*256 + k0_ + c80));           \
      asm volatile("cp.async.cg.shared.global [%0],[%1],16;\n"                   \
                   :: "r"(sb0), "l"(Bb + (size_t)r0*256 + k0_ + c80));           \
      asm volatile("cp.async.cg.shared.global [%0],[%1],16;\n"                   \
                   :: "r"(sa1), "l"(Ab + (size_t)r1*256 + k0_ + c81));           \
      asm volatile("cp.async.cg.shared.global [%0],[%1],16;\n"                   \
                   :: "r"(sb1), "l"(Bb + (size_t)r1*256 + k0_ + c81));           \
      asm volatile("cp.async.commit_group;\n");                                  \
    }

  FC_ISSUE(0, 0)
  FC_ISSUE(1, 1)

  for (int c = 0; c < 8; c++){
    int s = c & 1;
    asm volatile("cp.async.wait_group 1;\n" ::: "memory");
    __syncthreads();
    wmma::fragment<wmma::matrix_a,16,16,16,__nv_bfloat16,wmma::row_major> af[2][4];
    wmma::fragment<wmma::matrix_b,16,16,16,__nv_bfloat16,wmma::col_major> bf[2][2];
    #pragma unroll
    for (int kk = 0; kk < 2; kk++){
      #pragma unroll
      for (int i = 0; i < 4; i++) wmma::load_matrix_sync(af[kk][i], &As[s][wm*64+i*16][kk*16], 40);
      #pragma unroll
      for (int jj = 0; jj < 2; jj++) wmma::load_matrix_sync(bf[kk][jj], &Bs[s][wn*32+jj*16][kk*16], 40);
    }
    __syncthreads();
    if (c + 2 < 8) FC_ISSUE(s, c+2)
    #pragma unroll
    for (int kk = 0; kk < 2; kk++)
      #pragma unroll
      for (int i = 0; i < 4; i++)
        #pragma unroll
        for (int jj = 0; jj < 2; jj++)
          wmma::mma_sync(acc[i][jj], af[kk][i], bf[kk][jj], acc[i][jj]);
  }
  #undef FC_ISSUE

  int er = lane >> 1, ec = (lane & 1)*8;
  #pragma unroll
  for (int i = 0; i < 4; i++){
    #pragma unroll
    for (int jj = 0; jj < 2; jj++){
      wmma::store_matrix_sync(&stg[warp][0][0], acc[i][jj], 20, wmma::mem_row_major);
      __syncwarp();
      int mm = bm*128 + wm*64 + i*16 + er;
      int n0 = bn*128 + wn*32 + jj*16 + ec;
      int orow = (mm & 15)*Tsz + (mm >> 4);
      float4 v0 = *(float4*)&stg[warp][er][ec];
      float4 v1 = *(float4*)&stg[warp][er][ec+4];
      v0.x += bias[n0];   v0.y += bias[n0+1]; v0.z += bias[n0+2]; v0.w += bias[n0+3];
      v1.x += bias[n0+4]; v1.y += bias[n0+5]; v1.z += bias[n0+6]; v1.w += bias[n0+7];
      *(float4*)&out[(size_t)orow*Vsz + n0]     = v0;
      *(float4*)&out[(size_t)orow*Vsz + n0 + 4] = v1;
      __syncwarp();
    }
  }
}

// ---------------- in-place log_softmax, row register-resident ----------------
__global__ __launch_bounds__(1024) void lsm_kernel(float* __restrict__ out){
  __shared__ float red[32];
  float4* p4 = (float4*)(out + (size_t)blockIdx.x*Vsz);
  int tid = threadIdx.x;
  float4 v[8];
  float m = -3.4e38f;
  #pragma unroll
  for (int i = 0; i < 8; i++){
    int idx = tid + i*1024;
    if (idx < Vsz/4){
      v[i] = p4[idx];
      m = fmaxf(m, fmaxf(fmaxf(v[i].x, v[i].y), fmaxf(v[i].z, v[i].w)));
    }
  }
  #pragma unroll
  for (int o = 16; o; o >>= 1) m = fmaxf(m, __shfl_xor_sync(0xffffffffu, m, o));
  if ((tid & 31) == 0) red[tid >> 5] = m;
  __syncthreads();
  float mm = red[0];
  #pragma unroll
  for (int ww = 1; ww < 32; ww++) mm = fmaxf(mm, red[ww]);
  __syncthreads();
  float s = 0.f;
  #pragma unroll
  for (int i = 0; i < 8; i++){
    int idx = tid + i*1024;
    if (idx < Vsz/4)
      s += __expf(v[i].x-mm) + __expf(v[i].y-mm) + __expf(v[i].z-mm) + __expf(v[i].w-mm);
  }
  #pragma unroll
  for (int o = 16; o; o >>= 1) s += __shfl_xor_sync(0xffffffffu, s, o);
  if ((tid & 31) == 0) red[tid >> 5] = s;
  __syncthreads();
  float ss = 0.f;
  #pragma unroll
  for (int ww = 0; ww < 32; ww++) ss += red[ww];
  float lse = mm + logf(ss);
  #pragma unroll
  for (int i = 0; i < 8; i++){
    int idx = tid + i*1024;
    if (idx < Vsz/4){
      float4 o4 = v[i];
      o4.x -= lse; o4.y -= lse; o4.z -= lse; o4.w -= lse;
      p4[idx] = o4;
    }
  }
}

extern "C" void kernel_launch(void* const* d_in, const int* in_sizes, int n_in,
                              void* d_out, int out_size) {
  const int*   x    = (const int*)  d_in[0];
  const float* emb  = (const float*)d_in[1];
  const float* Wi0  = (const float*)d_in[2];
  const float* Wh0  = (const float*)d_in[3];
  const float* b0   = (const float*)d_in[4];
  const float* Wi1  = (const float*)d_in[5];
  const float* Wh1  = (const float*)d_in[6];
  const float* b1   = (const float*)d_in[7];
  const float* Wi2  = (const float*)d_in[8];
  const float* Wh2  = (const float*)d_in[9];
  const float* b2   = (const float*)d_in[10];
  const float* fcW  = (const float*)d_in[11];
  const float* fcb  = (const float*)d_in[12];
  float* out = (float*)d_out;

  // launch order arranged so ncu (-s 5 -c 1) captures scan_kernel (index 5)
  embed_kernel<<<Msz, 256>>>(x, emb);          // 0
  padwi0_kernel<<<G4, 256>>>(Wi0);             // 1

  dim3 xg(16, 64);
  xproj_kernel<<<xg, 256>>>(0, Wi0, b0);       // 2
  scan_kernel<<<64, 512>>>(Wh0, 0);            // 3
  xproj_kernel<<<xg, 256>>>(1, Wi1, b1);       // 4
  scan_kernel<<<64, 512>>>(Wh1, 0);            // 5  <-- profiled
  xproj_kernel<<<xg, 256>>>(1, Wi2, b2);       // 6
  scan_kernel<<<64, 512>>>(Wh2, 1);            // 7  writes g_hb directly

  convwb_kernel<<<Vsz, 256>>>(fcW);            // 8
  dim3 fg(Vsz/128, Msz/128);
  fc_kernel<<<fg, 256>>>(fcb, out);            // 9
  lsm_kernel<<<Msz, 1024>>>(out);              // 10
}

// round 11
// speedup vs baseline: 2.5734x; 1.0332x over previous
#include <cuda_runtime.h>
#include <cuda_bf16.h>
#include <mma.h>
#include <cstdint>
using namespace nvcuda;
typedef unsigned long long ull;
typedef unsigned int u32;

#define Bsz 16
#define Tsz 256
#define Esz 200
#define Hsz 256
#define Vsz 32000
#define G4  1024
#define Msz 4096   // B*T rows, time-major: r = t*16 + b

__device__ float g_x[Msz*Hsz];
__device__ float g_xg[Msz*G4];
__device__ float g_hall[Msz*Hsz];
__device__ float g_wi0p[G4*Hsz];
__device__ __nv_bfloat16 g_hb[Msz*Hsz];
__device__ __nv_bfloat16 g_wb[(size_t)Vsz*Hsz];

__device__ __forceinline__ float sigmoidf_(float x){ return 1.f/(1.f+__expf(-x)); }
__device__ __forceinline__ float tanhf_(float x){ return 1.f - 2.f/(__expf(2.f*x)+1.f); }

__device__ __forceinline__ ull pk2(float a, float b){
  ull r; asm("mov.b64 %0,{%1,%2};" : "=l"(r) : "f"(a), "f"(b)); return r;
}
__device__ __forceinline__ void upk2(ull v, float& a, float& b){
  asm("mov.b64 {%0,%1},%2;" : "=f"(a), "=f"(b) : "l"(v));
}
__device__ __forceinline__ ull ffma2(ull a, ull b, ull c){
  ull d; asm("fma.rn.f32x2 %0,%1,%2,%3;" : "=l"(d) : "l"(a), "l"(b), "l"(c)); return d;
}

// ---------------- prep ----------------
__global__ void embed_kernel(const int* __restrict__ x, const float* __restrict__ emb){
  int idx = blockIdx.x*256 + threadIdx.x;
  int r = idx >> 8, k = idx & 255;
  int t = r >> 4, b = r & 15;
  float v = 0.f;
  if (k < Esz) v = emb[(size_t)x[b*Tsz + t]*Esz + k];
  g_x[idx] = v;
}

__global__ void padwi0_kernel(const float* __restrict__ Wi0){
  int idx = blockIdx.x*256 + threadIdx.x;
  int j = idx >> 8, k = idx & 255;
  g_wi0p[idx] = (k < Esz) ? Wi0[j*Esz + k] : 0.f;
}

__global__ void convwb_kernel(const float* __restrict__ fcW){
  size_t idx = (size_t)blockIdx.x*256 + threadIdx.x;
  g_wb[idx] = __float2bfloat16(fcW[idx]);
}

// ---------------- input-proj GEMM: g_xg[r][n] = X[r]·W[n] + bias[n] ----------------
__global__ __launch_bounds__(256) void xproj_kernel(int sel,
                                                    const float* __restrict__ Wext,
                                                    const float* __restrict__ bias){
  const float* __restrict__ X = sel ? g_hall : g_x;
  const float* __restrict__ W = sel ? Wext  : g_wi0p;
  __shared__ float As[16][64];
  __shared__ float Bs[16][64];
  int tid = threadIdx.x;
  int tx = tid & 15, ty = tid >> 4;
  int m0 = blockIdx.y*64, n0 = blockIdx.x*64;
  int lr = tid >> 2, lc = (tid & 3)*4;
  float acc[4][4] = {};
  for (int k0 = 0; k0 < 256; k0 += 16){
    float4 xv = *(const float4*)&X[(m0+lr)*256 + k0 + lc];
    float4 wv = *(const float4*)&W[(n0+lr)*256 + k0 + lc];
    __syncthreads();
    As[lc][lr]=xv.x; As[lc+1][lr]=xv.y; As[lc+2][lr]=xv.z; As[lc+3][lr]=xv.w;
    Bs[lc][lr]=wv.x; Bs[lc+1][lr]=wv.y; Bs[lc+2][lr]=wv.z; Bs[lc+3][lr]=wv.w;
    __syncthreads();
    #pragma unroll
    for (int k = 0; k < 16; k++){
      float4 a = *(float4*)&As[k][ty*4];
      float4 b = *(float4*)&Bs[k][tx*4];
      acc[0][0]+=a.x*b.x; acc[0][1]+=a.x*b.y; acc[0][2]+=a.x*b.z; acc[0][3]+=a.x*b.w;
      acc[1][0]+=a.y*b.x; acc[1][1]+=a.y*b.y; acc[1][2]+=a.y*b.z; acc[1][3]+=a.y*b.w;
      acc[2][0]+=a.z*b.x; acc[2][1]+=a.z*b.y; acc[2][2]+=a.z*b.z; acc[2][3]+=a.z*b.w;
      acc[3][0]+=a.w*b.x; acc[3][1]+=a.w*b.y; acc[3][2]+=a.w*b.z; acc[3][3]+=a.w*b.w;
    }
  }
  #pragma unroll
  for (int i = 0; i < 4; i++){
    int mrow = m0 + ty*4 + i;
    #pragma unroll
    for (int j = 0; j < 4; j++){
      int n = n0 + tx*4 + j;
      g_xg[mrow*G4 + n] = acc[i][j] + bias[n];
    }
  }
}

// ---------------- LSTM scan: 8-CTA cluster, TWO batches, ILP-interleaved step ----------------
// grid = 64 CTAs = 8 clusters; cluster c owns batches 2c, 2c+1.
// last==1: write bf16 h into g_hb (final layer) instead of f32 g_hall.
__global__ void __launch_bounds__(512,1) __cluster_dims__(8,1,1)
scan_kernel(const float* __restrict__ Wh, int last){
  __shared__ __align__(16) float hs[2][2][256];  // [batch][pingpong][h]
  __shared__ __align__(8)  ull mbar[2][2];       // [batch][pingpong]
  int tid = threadIdx.x;
  int w = tid >> 5, l = tid & 31;
  int g4 = l >> 3, kl = l & 7;
  u32 rank; asm("mov.u32 %0, %%cluster_ctarank;" : "=r"(rank));
  int c = blockIdx.x >> 3;
  int j = (int)rank;

  // register-resident weights: 2 gate-rows x 8 chunks x 2 f32x2 (shared by both batches)
  ull wgt[2][8][2];
  #pragma unroll
  for (int r = 0; r < 2; r++){
    int rg = 2*g4 + r;             // 0..7
    int u = rg >> 2, gate = rg & 3;
    int n = 32*j + 2*w + u;
    const float4* Wr = (const float4*)(Wh + (gate*256 + n)*256);
    #pragma unroll
    for (int m = 0; m < 8; m++){
      float4 v = Wr[kl + 8*m];
      wgt[r][m][0] = pk2(v.x, v.y);
      wgt[r][m][1] = pk2(v.z, v.w);
    }
  }
  if (tid < 256){ hs[0][0][tid] = 0.f; hs[1][0][tid] = 0.f; }

  u32 hbase, mbase;
  asm("{.reg .u64 t; cvta.to.shared.u64 t,%1; cvt.u32.u64 %0,t;}" : "=r"(hbase) : "l"(&hs[0][0][0]));
  asm("{.reg .u64 t; cvta.to.shared.u64 t,%1; cvt.u32.u64 %0,t;}" : "=r"(mbase) : "l"(&mbar[0][0]));

  if (tid == 0){
    #pragma unroll
    for (int q = 0; q < 4; q++){
      asm volatile("mbarrier.init.shared.b64 [%0],%1;" :: "r"(mbase + q*8u), "r"(1) : "memory");
      asm volatile("mbarrier.arrive.expect_tx.shared.b64 _,[%0],%1;" :: "r"(mbase + q*8u), "r"(1024) : "memory");
    }
  }
  __syncthreads();

  bool act = ((l & 15) == 0);      // lanes 0 and 16
  int u_loc = l >> 4;
  int n_act = 32*j + 2*w + u_loc;
  float creg0 = 0.f, creg1 = 0.f;
  float xgc[2][4] = {};
  float xgn[2][4] = {};
  if (act){
    #pragma unroll
    for (int bb = 0; bb < 2; bb++){
      int b = 2*c + bb;
      #pragma unroll
      for (int g = 0; g < 4; g++){
        xgc[bb][g] = __ldg(&g_xg[(0*16+b)*G4 + g*256 + n_act]);
        xgn[bb][g] = __ldg(&g_xg[(1*16+b)*G4 + g*256 + n_act]);
      }
    }
  }

  // one cluster sync: mbarrier init/arm + hs zeros visible before any remote st.async
  asm volatile("barrier.cluster.arrive.aligned;" ::: "memory");
  asm volatile("barrier.cluster.wait.aligned;" ::: "memory");

  for (int t = 0; t < 256; t++){
    // ---- phase 1: both waits up front ----
    if (t){
      u32 par = ((u32)(t - 1) >> 1) & 1u;
      #pragma unroll
      for (int bb = 0; bb < 2; bb++){
        u32 ma = mbase + (u32)bb*16u + (u32)(t & 1)*8u;
        u32 done;
        asm volatile(
          "{\n\t.reg .pred p;\n"
          "\tmbarrier.try_wait.parity.acquire.cta.shared::cta.b64 p,[%1],%2;\n"
          "\tselp.b32 %0,1,0,p;\n\t}"
          : "=r"(done) : "r"(ma), "r"(par) : "memory");
        if (!done){
          asm volatile(
            "{\n\t.reg .pred P1;\n"
            "WL%=:\n\tmbarrier.try_wait.parity.acquire.cta.shared::cta.b64 P1,[%0],%1,0x989680;\n"
            "\t@P1 bra WD%=;\n"
            "\tbra.uni WL%=;\n"
            "WD%=:\n\t}"
            :: "r"(ma), "r"(par) : "memory");
        }
      }
      if (tid == 0){
        asm volatile("mbarrier.arrive.expect_tx.shared.b64 _,[%0],%1;"
                     :: "r"(mbase + (u32)(t & 1)*8u), "r"(1024) : "memory");
        asm volatile("mbarrier.arrive.expect_tx.shared.b64 _,[%0],%1;"
                     :: "r"(mbase + 16u + (u32)(t & 1)*8u), "r"(1024) : "memory");
      }
    }
    // ---- phase 2: both batches' matvecs interleaved (4 independent chains) ----
    u32 rb0 = hbase + (u32)(t & 1)*1024u;
    u32 rb1 = rb0 + 2048u;
    ull p00 = 0ull, p01 = 0ull, p10 = 0ull, p11 = 0ull;
    #pragma unroll
    for (int m = 0; m < 8; m++){
      u32 off = (u32)(kl + 8*m)*16u;
      ull h0, h1, h2, h3;
      asm("ld.shared.v2.u64 {%0,%1},[%2];" : "=l"(h0), "=l"(h1) : "r"(rb0 + off));
      asm("ld.shared.v2.u64 {%0,%1},[%2];" : "=l"(h2), "=l"(h3) : "r"(rb1 + off));
      p00 = ffma2(wgt[0][m][0], h0, p00);
      p10 = ffma2(wgt[0][m][0], h2, p10);
      p01 = ffma2(wgt[1][m][0], h0, p01);
      p11 = ffma2(wgt[1][m][0], h2, p11);
      p00 = ffma2(wgt[0][m][1], h1, p00);
      p10 = ffma2(wgt[0][m][1], h3, p10);
      p01 = ffma2(wgt[1][m][1], h1, p01);
      p11 = ffma2(wgt[1][m][1], h3, p11);
    }
    float s00, s01, s10, s11, lo, hi;
    upk2(p00, lo, hi); s00 = lo + hi;
    upk2(p01, lo, hi); s01 = lo + hi;
    upk2(p10, lo, hi); s10 = lo + hi;
    upk2(p11, lo, hi); s11 = lo + hi;
    #pragma unroll
    for (int off = 1; off < 8; off <<= 1){
      s00 += __shfl_xor_sync(0xffffffffu, s00, off);
      s01 += __shfl_xor_sync(0xffffffffu, s01, off);
      s10 += __shfl_xor_sync(0xffffffffu, s10, off);
      s11 += __shfl_xor_sync(0xffffffffu, s11, off);
    }
    float gg0 = __shfl_xor_sync(0xffffffffu, s00, 8);
    float go0 = __shfl_xor_sync(0xffffffffu, s01, 8);
    float gg1 = __shfl_xor_sync(0xffffffffu, s10, 8);
    float go1 = __shfl_xor_sync(0xffffffffu, s11, 8);
    // ---- phase 3: activations (act lanes), both batches ----
    float hv0 = 0.f, hv1 = 0.f;
    if (act){
      float i0 = sigmoidf_(s00 + xgc[0][0]);
      float f0 = sigmoidf_(s01 + xgc[0][1]);
      float c0 = tanhf_(gg0 + xgc[0][2]);
      float o0 = sigmoidf_(go0 + xgc[0][3]);
      float i1 = sigmoidf_(s10 + xgc[1][0]);
      float f1 = sigmoidf_(s11 + xgc[1][1]);
      float c1 = tanhf_(gg1 + xgc[1][2]);
      float o1 = sigmoidf_(go1 + xgc[1][3]);
      creg0 = f0*creg0 + i0*c0;
      creg1 = f1*creg1 + i1*c1;
      hv0 = o0*tanhf_(creg0);
      hv1 = o1*tanhf_(creg1);
    }
    // ---- phase 4: distributed fan-out (lanes 0-7 / 16-23, one rank each) ----
    if (t < 255){
      u32 hb0 = __shfl_sync(0xffffffffu, __float_as_uint(hv0), l & 16);
      u32 hb1 = __shfl_sync(0xffffffffu, __float_as_uint(hv1), l & 16);
      if ((l & 8) == 0){
        int n_st = 32*j + 2*w + (l >> 4);
        u32 pr = (u32)(l & 7);
        u32 ha0 = hbase + (u32)((t+1) & 1)*1024u + (u32)n_st*4u;
        u32 ha1 = ha0 + 2048u;
        u32 me0 = mbase + (u32)((t+1) & 1)*8u;
        u32 me1 = me0 + 16u;
        u32 ra0, rm0, ra1, rm1;
        asm("mapa.shared::cluster.u32 %0,%1,%2;" : "=r"(ra0) : "r"(ha0), "r"(pr));
        asm("mapa.shared::cluster.u32 %0,%1,%2;" : "=r"(rm0) : "r"(me0), "r"(pr));
        asm("mapa.shared::cluster.u32 %0,%1,%2;" : "=r"(ra1) : "r"(ha1), "r"(pr));
        asm("mapa.shared::cluster.u32 %0,%1,%2;" : "=r"(rm1) : "r"(me1), "r"(pr));
        asm volatile("st.async.shared::cluster.mbarrier::complete_tx::bytes.b32 [%0],%1,[%2];"
                     :: "r"(ra0), "r"(hb0), "r"(rm0) : "memory");
        asm volatile("st.async.shared::cluster.mbarrier::complete_tx::bytes.b32 [%0],%1,[%2];"
                     :: "r"(ra1), "r"(hb1), "r"(rm1) : "memory");
      }
    }
    // ---- phase 5: global output + next-xg prefetch (act lanes) ----
    if (act){
      int b0g = 2*c, b1g = 2*c + 1;
      if (last){
        g_hb[(t*16+b0g)*256 + n_act] = __float2bfloat16(hv0);
        g_hb[(t*16+b1g)*256 + n_act] = __float2bfloat16(hv1);
      } else {
        g_hall[(t*16+b0g)*256 + n_act] = hv0;
        g_hall[(t*16+b1g)*256 + n_act] = hv1;
      }
      #pragma unroll
      for (int g = 0; g < 4; g++){
        xgc[0][g] = xgn[0][g];
        xgc[1][g] = xgn[1][g];
      }
      if (t + 2 < 256){
        #pragma unroll
        for (int g = 0; g < 4; g++){
          xgn[0][g] = __ldg(&g_xg[((t+2)*16+b0g)*G4 + g*256 + n_act]);
          xgn[1][g] = __ldg(&g_xg[((t+2)*16+b1g)*G4 + g*256 + n_act]);
        }
      }
    }
  }
  // all CTAs stay alive until peers stop storing into this CTA's smem
  asm volatile("barrier.cluster.arrive.aligned;" ::: "memory");
  asm volatile("barrier.cluster.wait.aligned;" ::: "memory");
}

// ---------------- FC GEMM bf16 WMMA, cp.async double-buffered ----------------
__global__ __launch_bounds__(256) void fc_kernel(const float* __restrict__ bias,
                                                 float* __restrict__ out){
  __shared__ __nv_bfloat16 As[2][128][40];
  __shared__ __nv_bfloat16 Bs[2][128][40];
  __shared__ float stg[8][16][20];
  int bn = blockIdx.x, bm = blockIdx.y;
  int tid = threadIdx.x;
  int warp = tid >> 5, lane = tid & 31;
  int wm = warp >> 2, wn = warp & 3;     // 2 x 4 warps; warp tile 64(M) x 32(N)
  const __nv_bfloat16* Ab = g_hb + (size_t)(bm*128)*256;
  const __nv_bfloat16* Bb = g_wb + (size_t)(bn*128)*256;

  int cid0 = tid*2;
  int r0 = cid0 >> 2,      c80 = (cid0 & 3)*8;
  int r1 = (cid0+1) >> 2,  c81 = ((cid0+1) & 3)*8;

  wmma::fragment<wmma::accumulator,16,16,16,float> acc[4][2];
  #pragma unroll
  for (int i = 0; i < 4; i++)
    #pragma unroll
    for (int jj = 0; jj < 2; jj++) wmma::fill_fragment(acc[i][jj], 0.f);

  #define FC_ISSUE(stage, c)                                                     \
    {                                                                            \
      int k0_ = (c)*32;                                                          \
      u32 sa0 = (u32)__cvta_generic_to_shared(&As[stage][r0][c80]);              \
      u32 sb0 = (u32)__cvta_generic_to_shared(&Bs[stage][r0][c80]);              \
      u32 sa1 = (u32)__cvta_generic_to_shared(&As[stage][r1][c81]);              \
      u32 sb1 = (u32)__cvta_generic_to_shared(&Bs[stage][r1][c81]);              \
      asm volatile("cp.async.cg.shared.global [%0],[%1],16;\n"                   \
                   :: "r"(sa0), "l"(Ab + (size_t)r0*256 + k0_ + c80));           \
      asm volatile("cp.async.cg.shared.global [%0],[%1],16;\n"                   \
                   :: "r"(sb0), "l"(Bb + (size_t)r0*256 + k0_ + c80));           \
      asm volatile("cp.async.cg.shared.global [%0],[%1],16;\n"                   \
                   :: "r"(sa1), "l"(Ab + (size_t)r1*256 + k0_ + c81));           \
      asm volatile("cp.async.cg.shared.global [%0],[%1],16;\n"                   \
                   :: "r"(sb1), "l"(Bb + (size_t)r1*256 + k0_ + c81));           \
      asm volatile("cp.async.commit_group;\n");                                  \
    }

  FC_ISSUE(0, 0)
  FC_ISSUE(1, 1)

  for (int c = 0; c < 8; c++){
    int s = c & 1;
    asm volatile("cp.async.wait_group 1;\n" ::: "memory");
    __syncthreads();
    wmma::fragment<wmma::matrix_a,16,16,16,__nv_bfloat16,wmma::row_major> af[2][4];
    wmma::fragment<wmma::matrix_b,16,16,16,__nv_bfloat16,wmma::col_major> bf[2][2];
    #pragma unroll
    for (int kk = 0; kk < 2; kk++){
      #pragma unroll
      for (int i = 0; i < 4; i++) wmma::load_matrix_sync(af[kk][i], &As[s][wm*64+i*16][kk*16], 40);
      #pragma unroll
      for (int jj = 0; jj < 2; jj++) wmma::load_matrix_sync(bf[kk][jj], &Bs[s][wn*32+jj*16][kk*16], 40);
    }
    __syncthreads();
    if (c + 2 < 8) FC_ISSUE(s, c+2)
    #pragma unroll
    for (int kk = 0; kk < 2; kk++)
      #pragma unroll
      for (int i = 0; i < 4; i++)
        #pragma unroll
        for (int jj = 0; jj < 2; jj++)
          wmma::mma_sync(acc[i][jj], af[kk][i], bf[kk][jj], acc[i][jj]);
  }
  #undef FC_ISSUE

  int er = lane >> 1, ec = (lane & 1)*8;
  #pragma unroll
  for (int i = 0; i < 4; i++){
    #pragma unroll
    for (int jj = 0; jj < 2; jj++){
      wmma::store_matrix_sync(&stg[warp][0][0], acc[i][jj], 20, wmma::mem_row_major);
      __syncwarp();
      int mm = bm*128 + wm*64 + i*16 + er;
      int n0 = bn*128 + wn*32 + jj*16 + ec;
      int orow = (mm & 15)*Tsz + (mm >> 4);
      float4 v0 = *(float4*)&stg[warp][er][ec];
      float4 v1 = *(float4*)&stg[warp][er][ec+4];
      v0.x += bias[n0];   v0.y += bias[n0+1]; v0.z += bias[n0+2]; v0.w += bias[n0+3];
      v1.x += bias[n0+4]; v1.y += bias[n0+5]; v1.z += bias[n0+6]; v1.w += bias[n0+7];
      *(float4*)&out[(size_t)orow*Vsz + n0]     = v0;
      *(float4*)&out[(size_t)orow*Vsz + n0 + 4] = v1;
      __syncwarp();
    }
  }
}

// ---------------- in-place log_softmax, row register-resident ----------------
__global__ __launch_bounds__(1024) void lsm_kernel(float* __restrict__ out){
  __shared__ float red[32];
  float4* p4 = (float4*)(out + (size_t)blockIdx.x*Vsz);
  int tid = threadIdx.x;
  float4 v[8];
  float m = -3.4e38f;
  #pragma unroll
  for (int i = 0; i < 8; i++){
    int idx = tid + i*1024;
    if (idx < Vsz/4){
      v[i] = p4[idx];
      m = fmaxf(m, fmaxf(fmaxf(v[i].x, v[i].y), fmaxf(v[i].z, v[i].w)));
    }
  }
  #pragma unroll
  for (int o = 16; o; o >>= 1) m = fmaxf(m, __shfl_xor_sync(0xffffffffu, m, o));
  if ((tid & 31) == 0) red[tid >> 5] = m;
  __syncthreads();
  float mm = red[0];
  #pragma unroll
  for (int ww = 1; ww < 32; ww++) mm = fmaxf(mm, red[ww]);
  __syncthreads();
  float s = 0.f;
  #pragma unroll
  for (int i = 0; i < 8; i++){
    int idx = tid + i*1024;
    if (idx < Vsz/4)
      s += __expf(v[i].x-mm) + __expf(v[i].y-mm) + __expf(v[i].z-mm) + __expf(v[i].w-mm);
  }
  #pragma unroll
  for (int o = 16; o; o >>= 1) s += __shfl_xor_sync(0xffffffffu, s, o);
  if ((tid & 31) == 0) red[tid >> 5] = s;
  __syncthreads();
  float ss = 0.f;
  #pragma unroll
  for (int ww = 0; ww < 32; ww++) ss += red[ww];
  float lse = mm + logf(ss);
  #pragma unroll
  for (int i = 0; i < 8; i++){
    int idx = tid + i*1024;
    if (idx < Vsz/4){
      float4 o4 = v[i];
      o4.x -= lse; o4.y -= lse; o4.z -= lse; o4.w -= lse;
      p4[idx] = o4;
    }
  }
}

extern "C" void kernel_launch(void* const* d_in, const int* in_sizes, int n_in,
                              void* d_out, int out_size) {
  const int*   x    = (const int*)  d_in[0];
  const float* emb  = (const float*)d_in[1];
  const float* Wi0  = (const float*)d_in[2];
  const float* Wh0  = (const float*)d_in[3];
  const float* b0   = (const float*)d_in[4];
  const float* Wi1  = (const float*)d_in[5];
  const float* Wh1  = (const float*)d_in[6];
  const float* b1   = (const float*)d_in[7];
  const float* Wi2  = (const float*)d_in[8];
  const float* Wh2  = (const float*)d_in[9];
  const float* b2   = (const float*)d_in[10];
  const float* fcW  = (const float*)d_in[11];
  const float* fcb  = (const float*)d_in[12];
  float* out = (float*)d_out;

  // launch order arranged so ncu (-s 5 -c 1) captures scan_kernel (index 5)
  embed_kernel<<<Msz, 256>>>(x, emb);          // 0
  padwi0_kernel<<<G4, 256>>>(Wi0);             // 1

  dim3 xg(16, 64);
  xproj_kernel<<<xg, 256>>>(0, Wi0, b0);       // 2
  scan_kernel<<<64, 512>>>(Wh0, 0);            // 3
  xproj_kernel<<<xg, 256>>>(1, Wi1, b1);       // 4
  scan_kernel<<<64, 512>>>(Wh1, 0);            // 5  <-- profiled
  xproj_kernel<<<xg, 256>>>(1, Wi2, b2);       // 6
  scan_kernel<<<64, 512>>>(Wh2, 1);            // 7  writes g_hb directly

  convwb_kernel<<<Vsz, 256>>>(fcW);            // 8
  dim3 fg(Vsz/128, Msz/128);
  fc_kernel<<<fg, 256>>>(fcb, out);            // 9
  lsm_kernel<<<Msz, 1024>>>(out);              // 10
}